// round 10
// baseline (speedup 1.0000x reference)
#include <cuda_runtime.h>
#include <math.h>
#include <stdint.h>

// ---------------- problem constants ----------------
#define HDIM  384
#define HHALF 192
constexpr int   MAXN   = 40000;
constexpr int   MAXD   = 20000;
constexpr int   MAXE   = 800000;
constexpr int   MAXNNZ = 800000;
constexpr float ALPHA  = 0.65f;
constexpr float LN_EPS = 1e-5f;

// weight split pool offsets (u32 units). Layout is TRANSPOSED: Wt[n][K/2] (n-major).
constexpr int OFF_W1  = 0;
constexpr int OFF_W2  = 73728;
constexpr int OFF_W3  = 147456;
constexpr int OFF_GW2 = 221184;
constexpr int OFF_MW1 = 294912;
constexpr int OFF_GW1 = 368640;   // 384 n x 384 kp (K=768)
constexpr int OFF_MW2 = 516096;   // 192 n x 192 kp
constexpr int WPOOL   = 552960;

// ---------------- static scratch ----------------
__device__ float g_buf1[(size_t)MAXN * HDIM];
__device__ float g_buf2[(size_t)MAXN * HDIM];
__device__ float g_docH [(size_t)MAXD * HDIM];
__device__ float g_docH0[(size_t)MAXD * HDIM];
__device__ float g_hidden[(size_t)MAXD * HDIM];
__device__ float g_doc  [(size_t)MAXD * HDIM];
__device__ float g_t2   [(size_t)MAXD * HHALF];

__device__ __align__(16) uint32_t g_Whi[WPOOL];
__device__ __align__(16) uint32_t g_Wlo[WPOOL];

__device__ int   g_Arp[MAXN + 1];
__device__ int   g_Awp[MAXN + 1];
__device__ int   g_Aci[MAXE];
__device__ float g_Av [MAXE];
__device__ int   g_Xrp[MAXD + 1];
__device__ int   g_Xwp[MAXD + 1];
__device__ int   g_Xci[MAXNNZ];
__device__ float g_Xv [MAXNNZ];

// ---------------- helpers ----------------
__device__ __forceinline__ float gelu_exact(float x) {
    return 0.5f * x * (1.0f + erff(x * 0.70710678118654752f));
}
__device__ __forceinline__ float sigmoidf_(float x) {
    return 1.0f / (1.0f + __expf(-x));
}
__device__ __forceinline__ uint32_t cvtbf2(float lo, float hi) {
    uint32_t r;
    asm("cvt.rn.bf16x2.f32 %0, %1, %2;" : "=r"(r) : "f"(hi), "f"(lo));
    return r;
}
__device__ __forceinline__ float bflo(uint32_t p) { return __uint_as_float(p << 16); }
__device__ __forceinline__ float bfhi(uint32_t p) { return __uint_as_float(p & 0xffff0000u); }
__device__ __forceinline__ void bsplit2(float x, float y, uint32_t& h, uint32_t& l) {
    h = cvtbf2(x, y);
    l = cvtbf2(x - bflo(h), y - bfhi(h));
}
__device__ __forceinline__ void mma_bf16(float* d, const uint32_t* a, const uint32_t* b) {
    asm volatile(
        "mma.sync.aligned.m16n8k16.row.col.f32.bf16.bf16.f32 "
        "{%0,%1,%2,%3}, {%4,%5,%6,%7}, {%8,%9}, {%0,%1,%2,%3};"
        : "+f"(d[0]), "+f"(d[1]), "+f"(d[2]), "+f"(d[3])
        : "r"(a[0]), "r"(a[1]), "r"(a[2]), "r"(a[3]), "r"(b[0]), "r"(b[1]));
}
__device__ __forceinline__ void ldsm_x4(uint32_t& r0, uint32_t& r1, uint32_t& r2, uint32_t& r3,
                                        uint32_t addr) {
    asm volatile("ldmatrix.sync.aligned.m8n8.x4.shared.b16 {%0,%1,%2,%3}, [%4];"
                 : "=r"(r0), "=r"(r1), "=r"(r2), "=r"(r3) : "r"(addr));
}
__device__ __forceinline__ void fma4(float4& a, float v, const float4& m) {
    a.x = fmaf(v, m.x, a.x);
    a.y = fmaf(v, m.y, a.y);
    a.z = fmaf(v, m.z, a.z);
    a.w = fmaf(v, m.w, a.w);
}

// ---------------- weight pre-split + transpose: W[K][NC] -> hi/lo Wt[n][K/2] ----------------
// 32x32 tile transpose via smem; both gmem sides coalesced.
__global__ void k_wsplit_t(const float* __restrict__ W, int KP, int NC,
                           uint32_t* __restrict__ hi, uint32_t* __restrict__ lo) {
    __shared__ uint32_t th[32][33], tl[32][33];
    const int kp0 = blockIdx.x * 32;
    const int n0  = blockIdx.y * 32;
    const int tx = threadIdx.x, ty = threadIdx.y;
    for (int i = ty; i < 32; i += 8) {
        int kp = kp0 + i, n = n0 + tx;
        float x = W[(size_t)(2 * kp) * NC + n];
        float y = W[(size_t)(2 * kp + 1) * NC + n];
        uint32_t h, l;
        bsplit2(x, y, h, l);
        th[i][tx] = h;
        tl[i][tx] = l;
    }
    __syncthreads();
    for (int i = ty; i < 32; i += 8) {
        int n = n0 + i, kp = kp0 + tx;
        hi[(size_t)n * KP + kp] = th[tx][i];
        lo[(size_t)n * KP + kp] = tl[tx][i];
    }
}

// ---------------- CSR build ----------------
__global__ void k_zero_i32(int* p, int n) {
    int i = blockIdx.x * blockDim.x + threadIdx.x;
    if (i < n) p[i] = 0;
}

__global__ void k_hist(const int* __restrict__ rows, int ne, int* __restrict__ cnt) {
    int e = blockIdx.x * blockDim.x + threadIdx.x;
    if (e < ne) atomicAdd(&cnt[rows[e]], 1);
}

__global__ void k_scan_excl(int* __restrict__ data, int n, int* __restrict__ wp) {
    __shared__ int sums[1024];
    int t = threadIdx.x;
    int C = (n + 1023) / 1024;
    int start = t * C;
    int end   = min(start + C, n);

    int s = 0;
    for (int i = start; i < end; i++) s += data[i];
    sums[t] = s;
    __syncthreads();

    for (int off = 1; off < 1024; off <<= 1) {
        int add = (t >= off) ? sums[t - off] : 0;
        __syncthreads();
        sums[t] += add;
        __syncthreads();
    }

    int run = sums[t] - s;
    for (int i = start; i < end; i++) {
        int c = data[i];
        data[i] = run;
        wp[i]   = run;
        run += c;
    }
    if (t == 1023) data[n] = sums[1023];
}

__global__ void k_scatter(const int* __restrict__ rows, const int* __restrict__ cols,
                          const float* __restrict__ vals, int ne,
                          int* __restrict__ wp, int* __restrict__ ci,
                          float* __restrict__ cv) {
    int e = blockIdx.x * blockDim.x + threadIdx.x;
    if (e < ne) {
        int pos = atomicAdd(&wp[rows[e]], 1);
        ci[pos] = cols[e];
        cv[pos] = vals[e];
    }
}

// ---------------- SpMM (CSR gather, float4, unroll-4) ----------------
__global__ void __launch_bounds__(96)
k_spmm(const int* __restrict__ rp, const int* __restrict__ ci,
       const float* __restrict__ cv, const float* __restrict__ M,
       float* __restrict__ out) {
    const int r = blockIdx.x;
    const int t = threadIdx.x;
    const int s = rp[r], e = rp[r + 1];
    const float4* __restrict__ M4 = (const float4*)M;
    float4 acc = make_float4(0.f, 0.f, 0.f, 0.f);

    int j = s;
    for (; j + 4 <= e; j += 4) {
        int   c0 = ci[j],     c1 = ci[j + 1], c2 = ci[j + 2], c3 = ci[j + 3];
        float v0 = cv[j],     v1 = cv[j + 1], v2 = cv[j + 2], v3 = cv[j + 3];
        float4 m0 = M4[(size_t)c0 * 96 + t];
        float4 m1 = M4[(size_t)c1 * 96 + t];
        float4 m2 = M4[(size_t)c2 * 96 + t];
        float4 m3 = M4[(size_t)c3 * 96 + t];
        fma4(acc, v0, m0);
        fma4(acc, v1, m1);
        fma4(acc, v2, m2);
        fma4(acc, v3, m3);
    }
    for (; j < e; j++) {
        float4 m = M4[(size_t)ci[j] * 96 + t];
        fma4(acc, cv[j], m);
    }
    ((float4*)(out + (size_t)r * HDIM))[t] = acc;
}

__global__ void __launch_bounds__(96)
k_spmm2(const int* __restrict__ rp, const int* __restrict__ ci,
        const float* __restrict__ cv,
        const float* __restrict__ Ma, const float* __restrict__ Mb,
        float* __restrict__ outA, float* __restrict__ outB) {
    const int r = blockIdx.x;
    const int t = threadIdx.x;
    const int s = rp[r], e = rp[r + 1];
    const float4* __restrict__ A4 = (const float4*)Ma;
    const float4* __restrict__ B4 = (const float4*)Mb;
    float4 accA = make_float4(0.f, 0.f, 0.f, 0.f);
    float4 accB = make_float4(0.f, 0.f, 0.f, 0.f);

    int j = s;
    for (; j + 2 <= e; j += 2) {
        int   c0 = ci[j],  c1 = ci[j + 1];
        float v0 = cv[j],  v1 = cv[j + 1];
        float4 a0 = A4[(size_t)c0 * 96 + t];
        float4 b0 = B4[(size_t)c0 * 96 + t];
        float4 a1 = A4[(size_t)c1 * 96 + t];
        float4 b1 = B4[(size_t)c1 * 96 + t];
        fma4(accA, v0, a0);
        fma4(accB, v0, b0);
        fma4(accA, v1, a1);
        fma4(accB, v1, b1);
    }
    for (; j < e; j++) {
        int   c = ci[j];
        float v = cv[j];
        float4 a = A4[(size_t)c * 96 + t];
        float4 b = B4[(size_t)c * 96 + t];
        fma4(accA, v, a);
        fma4(accB, v, b);
    }
    ((float4*)(outA + (size_t)r * HDIM))[t] = accA;
    ((float4*)(outB + (size_t)r * HDIM))[t] = accB;
}

// ---------------- bf16x2 split tensor-core GEMM with ldmatrix fragments ----------------
// C[M x NCOLS] = epilogue( A[M x K] @ W[K x NCOLS] ), A may be virtual concat [A1|A2].
// Weights pre-split TRANSPOSED: Wt[n][K/2] (bf16x2 k-pairs, n-major).
// Smem: A as [row][kpair] stride 12; B as [n][kpair] stride 12 — both ldmatrix-phase
// conflict-free. Fragments loaded with ldmatrix.x4: A 4 instrs, B 3+3 instrs per chunk
// (vs 40 LDS.32) — flips kernel from issue-bound to tensor-bound.
enum { EPI_LN_GELU = 0, EPI_GELU = 1, EPI_GATE = 2, EPI_GELU_LN = 3 };

template <int NCOLS, int EPI>
__global__ void __launch_bounds__(64 * (NCOLS / 48))
k_gemm(const float* __restrict__ A1, const float* __restrict__ A2,
       int K, int K1,
       const uint32_t* __restrict__ Whi, const uint32_t* __restrict__ Wlo,
       const float* __restrict__ bias,
       const float* __restrict__ gw, const float* __restrict__ bw,
       const float* __restrict__ aux1, const float* __restrict__ aux2,
       const float* __restrict__ res,
       float* __restrict__ out, int M) {
    constexpr int NWN     = NCOLS / 48;
    constexpr int THREADS = 64 * NWN;
    constexpr int BM = 64, BK = 16;
    constexpr int MT = 2, NT = 6;
    constexpr int AV4 = BM * BK / 4;      // 256 float4 (A tile)
    constexpr int BN4 = NCOLS * 2;        // uint4 per B part tile (NCOLS rows x 32B)
    constexpr int BITER = (BN4 + THREADS - 1) / THREADS;

    __shared__ uint32_t AsH[BM][12], AsL[BM][12];      // [row][kpair] stride 12
    __shared__ uint32_t BsH[NCOLS][12], BsL[NCOLS][12];// [n][kpair]  stride 12
    __shared__ float redS[2][32][NWN];
    __shared__ float redQ[2][32][NWN];

    const int tid  = threadIdx.x;
    const int lane = tid & 31;
    const int warp = tid >> 5;
    const int wm = warp & 1;
    const int wn = warp >> 1;
    const int g  = lane >> 2;
    const int t  = lane & 3;
    const int bm0 = blockIdx.x * BM;
    const int NC  = K / BK;
    const int KP  = K >> 1;

    float acc[MT][NT][4];
#pragma unroll
    for (int mt = 0; mt < MT; mt++)
#pragma unroll
        for (int nt = 0; nt < NT; nt++)
#pragma unroll
            for (int c = 0; c < 4; c++) acc[mt][nt][c] = 0.f;

    // ---- ldmatrix lane addresses (loop-invariant; single-buffered smem) ----
    // A x4: mats = (rows0-7,k0-7),(rows8-15,k0-7),(rows0-7,k8-15),(rows8-15,k8-15)
    const int rowoffA = (lane & 7) + 8 * ((lane >> 3) & 1);
    const int colA    = 4 * ((lane >> 4) & 1);
    uint32_t aAh[MT], aAl[MT];
#pragma unroll
    for (int mt = 0; mt < MT; mt++) {
        int r = wm * 32 + mt * 16 + rowoffA;
        aAh[mt] = (uint32_t)__cvta_generic_to_shared(&AsH[r][colA]);
        aAl[mt] = (uint32_t)__cvta_generic_to_shared(&AsL[r][colA]);
    }
    // B x4 (pair p covers nt=2p,2p+1): mats = (nt,k0-7),(nt,k8-15),(nt+1,k0-7),(nt+1,k8-15)
    const int noffB = (lane & 7) + 8 * ((lane >> 4) & 1);
    const int colB  = 4 * ((lane >> 3) & 1);
    uint32_t aBh[3], aBl[3];
#pragma unroll
    for (int p = 0; p < 3; p++) {
        int n = wn * 48 + p * 16 + noffB;
        aBh[p] = (uint32_t)__cvta_generic_to_shared(&BsH[n][colB]);
        aBl[p] = (uint32_t)__cvta_generic_to_shared(&BsL[n][colB]);
    }

    float4 pa;
    uint4  pbh[BITER], pbl[BITER];

    auto gload = [&](int k0) {
        const float* Ab;
        int kc, AW;
        if (k0 < K1) { Ab = A1; kc = k0; AW = K1; }
        else         { Ab = A2; kc = k0 - K1; AW = K - K1; }
        if (tid < AV4) {
            int row = tid >> 2, f4 = tid & 3;
            int grow = bm0 + row;
            if (grow < M)
                pa = *(const float4*)(Ab + (size_t)grow * AW + kc + 4 * f4);
            else
                pa = make_float4(0.f, 0.f, 0.f, 0.f);
        }
        const int kp0 = k0 >> 1;
#pragma unroll
        for (int i = 0; i < BITER; i++) {
            int idx = tid + i * THREADS;
            if (idx < BN4) {
                int n = idx >> 1, half = idx & 1;
                size_t off = (size_t)n * KP + kp0 + 4 * half;
                pbh[i] = *(const uint4*)(Whi + off);
                pbl[i] = *(const uint4*)(Wlo + off);
            }
        }
    };
    auto sstore = [&]() {
        if (tid < AV4) {
            int row = tid >> 2, f4 = tid & 3;
            uint32_t h0, l0, h1, l1;
            bsplit2(pa.x, pa.y, h0, l0);
            bsplit2(pa.z, pa.w, h1, l1);
            AsH[row][2 * f4]     = h0;
            AsH[row][2 * f4 + 1] = h1;
            AsL[row][2 * f4]     = l0;
            AsL[row][2 * f4 + 1] = l1;
        }
#pragma unroll
        for (int i = 0; i < BITER; i++) {
            int idx = tid + i * THREADS;
            if (idx < BN4) {
                int n = idx >> 1, half = idx & 1;
                *(uint4*)&BsH[n][4 * half] = pbh[i];
                *(uint4*)&BsL[n][4 * half] = pbl[i];
            }
        }
    };

    gload(0);
    sstore();
    __syncthreads();

    for (int c = 0; c < NC; c++) {
        if (c + 1 < NC) gload((c + 1) * BK);

        uint32_t ah[MT][4], al[MT][4], bh[NT][2];
        ldsm_x4(ah[0][0], ah[0][1], ah[0][2], ah[0][3], aAh[0]);
        ldsm_x4(ah[1][0], ah[1][1], ah[1][2], ah[1][3], aAh[1]);
        ldsm_x4(al[0][0], al[0][1], al[0][2], al[0][3], aAl[0]);
        ldsm_x4(al[1][0], al[1][1], al[1][2], al[1][3], aAl[1]);
#pragma unroll
        for (int p = 0; p < 3; p++)
            ldsm_x4(bh[2 * p][0], bh[2 * p][1], bh[2 * p + 1][0], bh[2 * p + 1][1], aBh[p]);

        // pass 1: ah * bh
#pragma unroll
        for (int nt = 0; nt < NT; nt++)
#pragma unroll
            for (int mt = 0; mt < MT; mt++)
                mma_bf16(acc[mt][nt], ah[mt], bh[nt]);
        // pass 2: al * bh
#pragma unroll
        for (int nt = 0; nt < NT; nt++)
#pragma unroll
            for (int mt = 0; mt < MT; mt++)
                mma_bf16(acc[mt][nt], al[mt], bh[nt]);
        // pass 3: ah * bl (bl loaded per nt-pair)
#pragma unroll
        for (int p = 0; p < 3; p++) {
            uint32_t bl[4];
            ldsm_x4(bl[0], bl[1], bl[2], bl[3], aBl[p]);
            mma_bf16(acc[0][2 * p],     ah[0], bl);
            mma_bf16(acc[1][2 * p],     ah[1], bl);
            mma_bf16(acc[0][2 * p + 1], ah[0], bl + 2);
            mma_bf16(acc[1][2 * p + 1], ah[1], bl + 2);
        }

        __syncthreads();
        if (c + 1 < NC) {
            sstore();
            __syncthreads();
        }
    }

    // -------- epilogues --------
    // acc[mt][nt][c]: row = wm*32 + mt*16 + 8*(c>>1) + g ; col = wn*48 + nt*8 + 2*t + (c&1)
    if constexpr (EPI == EPI_GELU) {
#pragma unroll
        for (int mt = 0; mt < MT; mt++)
#pragma unroll
            for (int d = 0; d < 2; d++) {
                int grow = bm0 + wm * 32 + mt * 16 + 8 * d + g;
                if (grow >= M) continue;
#pragma unroll
                for (int nt = 0; nt < NT; nt++) {
                    int col = wn * 48 + nt * 8 + 2 * t;
                    float v0 = acc[mt][nt][2 * d]     + (bias ? bias[col]     : 0.f);
                    float v1 = acc[mt][nt][2 * d + 1] + (bias ? bias[col + 1] : 0.f);
                    *(float2*)&out[(size_t)grow * NCOLS + col] =
                        make_float2(gelu_exact(v0), gelu_exact(v1));
                }
            }
    } else if constexpr (EPI == EPI_GATE) {
#pragma unroll
        for (int mt = 0; mt < MT; mt++)
#pragma unroll
            for (int d = 0; d < 2; d++) {
                int grow = bm0 + wm * 32 + mt * 16 + 8 * d + g;
                if (grow >= M) continue;
#pragma unroll
                for (int nt = 0; nt < NT; nt++) {
                    int col = wn * 48 + nt * 8 + 2 * t;
                    size_t idx = (size_t)grow * NCOLS + col;
                    float s0 = sigmoidf_(acc[mt][nt][2 * d]     + bias[col]);
                    float s1 = sigmoidf_(acc[mt][nt][2 * d + 1] + bias[col + 1]);
                    float2 h1 = *(const float2*)&aux1[idx];
                    float2 h0 = *(const float2*)&aux2[idx];
                    *(float2*)&out[idx] = make_float2(
                        s0 * h1.x + (1.f - s0) * h0.x,
                        s1 * h1.y + (1.f - s1) * h0.y);
                }
            }
    } else {
        float sm_[MT][2], sq_[MT][2];
#pragma unroll
        for (int mt = 0; mt < MT; mt++)
#pragma unroll
            for (int d = 0; d < 2; d++) { sm_[mt][d] = 0.f; sq_[mt][d] = 0.f; }

#pragma unroll
        for (int mt = 0; mt < MT; mt++)
#pragma unroll
            for (int nt = 0; nt < NT; nt++) {
                int col = wn * 48 + nt * 8 + 2 * t;
#pragma unroll
                for (int d = 0; d < 2; d++) {
                    float v0 = acc[mt][nt][2 * d];
                    float v1 = acc[mt][nt][2 * d + 1];
                    if constexpr (EPI == EPI_GELU_LN) {
                        v0 = gelu_exact(v0 + bias[col]);
                        v1 = gelu_exact(v1 + bias[col + 1]);
                        acc[mt][nt][2 * d] = v0;
                        acc[mt][nt][2 * d + 1] = v1;
                    }
                    sm_[mt][d] += v0 + v1;
                    sq_[mt][d] += v0 * v0 + v1 * v1;
                }
            }
#pragma unroll
        for (int mt = 0; mt < MT; mt++)
#pragma unroll
            for (int d = 0; d < 2; d++) {
                float s = sm_[mt][d], q = sq_[mt][d];
                s += __shfl_xor_sync(0xffffffffu, s, 1);
                q += __shfl_xor_sync(0xffffffffu, q, 1);
                s += __shfl_xor_sync(0xffffffffu, s, 2);
                q += __shfl_xor_sync(0xffffffffu, q, 2);
                sm_[mt][d] = s; sq_[mt][d] = q;
            }
        if (t == 0) {
#pragma unroll
            for (int mt = 0; mt < MT; mt++)
#pragma unroll
                for (int d = 0; d < 2; d++) {
                    int rr = mt * 16 + 8 * d + g;
                    redS[wm][rr][wn] = sm_[mt][d];
                    redQ[wm][rr][wn] = sq_[mt][d];
                }
        }
        __syncthreads();
#pragma unroll
        for (int mt = 0; mt < MT; mt++)
#pragma unroll
            for (int d = 0; d < 2; d++) {
                int rr = mt * 16 + 8 * d + g;
                float S = 0.f, Q = 0.f;
#pragma unroll
                for (int w = 0; w < NWN; w++) { S += redS[wm][rr][w]; Q += redQ[wm][rr][w]; }
                float mean = S * (1.0f / NCOLS);
                float var  = Q * (1.0f / NCOLS) - mean * mean;
                float rstd = rsqrtf(var + LN_EPS);
                int grow = bm0 + wm * 32 + rr;
                if (grow >= M) continue;
#pragma unroll
                for (int nt = 0; nt < NT; nt++) {
                    int col = wn * 48 + nt * 8 + 2 * t;
                    float nv0 = (acc[mt][nt][2 * d]     - mean) * rstd * gw[col]     + bw[col];
                    float nv1 = (acc[mt][nt][2 * d + 1] - mean) * rstd * gw[col + 1] + bw[col + 1];
                    float o0, o1;
                    if constexpr (EPI == EPI_LN_GELU) {
                        o0 = gelu_exact(nv0);
                        o1 = gelu_exact(nv1);
                        if (res) {
                            float2 rv = *(const float2*)&res[(size_t)grow * NCOLS + col];
                            o0 = (1.f - ALPHA) * rv.x + ALPHA * o0;
                            o1 = (1.f - ALPHA) * rv.y + ALPHA * o1;
                        }
                    } else {
                        o0 = nv0; o1 = nv1;
                    }
                    *(float2*)&out[(size_t)grow * NCOLS + col] = make_float2(o0, o1);
                }
            }
    }
}

// ---------------- final tiny classifier ----------------
__global__ void k_logits(const float* __restrict__ t2, const float* __restrict__ clsW,
                         const float* __restrict__ clsb, float* __restrict__ out, int D) {
    int warp = (blockIdx.x * blockDim.x + threadIdx.x) >> 5;
    int lane = threadIdx.x & 31;
    if (warp >= D) return;
    const float* r = t2 + (size_t)warp * HHALF;
    float a0 = 0.f, a1 = 0.f;
    for (int k = lane; k < HHALF; k += 32) {
        float x = r[k];
        a0 = fmaf(x, clsW[2 * k],     a0);
        a1 = fmaf(x, clsW[2 * k + 1], a1);
    }
    for (int off = 16; off > 0; off >>= 1) {
        a0 += __shfl_down_sync(0xffffffffu, a0, off);
        a1 += __shfl_down_sync(0xffffffffu, a1, off);
    }
    if (lane == 0) {
        out[2 * warp]     = a0 + clsb[0];
        out[2 * warp + 1] = a1 + clsb[1];
    }
}

// ---------------- launch ----------------
extern "C" void kernel_launch(void* const* d_in, const int* in_sizes, int n_in,
                              void* d_out, int out_size) {
    const int*   A_rows  = (const int*)  d_in[0];
    const int*   A_cols  = (const int*)  d_in[1];
    const float* A_vals  = (const float*)d_in[2];
    const int*   X_rows  = (const int*)  d_in[3];
    const int*   X_cols  = (const int*)  d_in[4];
    const float* X_vals  = (const float*)d_in[5];
    const float* emb     = (const float*)d_in[7];
    const float* W1      = (const float*)d_in[8];
    const float* W2      = (const float*)d_in[9];
    const float* W3      = (const float*)d_in[10];
    const float* g1      = (const float*)d_in[11];
    const float* b1      = (const float*)d_in[12];
    const float* g2      = (const float*)d_in[13];
    const float* b2      = (const float*)d_in[14];
    const float* g3      = (const float*)d_in[15];
    const float* b3      = (const float*)d_in[16];
    const float* mlp_W1  = (const float*)d_in[17];
    const float* mlp_b1  = (const float*)d_in[18];
    const float* mlp_g   = (const float*)d_in[19];
    const float* mlp_bn  = (const float*)d_in[20];
    const float* mlp_W2  = (const float*)d_in[21];
    const float* mlp_b2  = (const float*)d_in[22];
    const float* cls_W   = (const float*)d_in[23];
    const float* cls_b   = (const float*)d_in[24];
    const float* gate_W1 = (const float*)d_in[25];
    const float* gate_b1 = (const float*)d_in[26];
    const float* gate_W2 = (const float*)d_in[27];
    const float* gate_b2 = (const float*)d_in[28];

    const int E   = in_sizes[0];
    const int NNZ = in_sizes[3];
    const int N   = in_sizes[7] / HDIM;
    const int D   = out_size / 2;
    float* out = (float*)d_out;

    float *buf1, *buf2, *docH, *docH0, *hidden, *doc, *t2;
    int *Arp, *Awp, *Aci, *Xrp, *Xwp, *Xci;
    float *Av, *Xv;
    uint32_t *Whi, *Wlo;
    cudaGetSymbolAddress((void**)&buf1,   g_buf1);
    cudaGetSymbolAddress((void**)&buf2,   g_buf2);
    cudaGetSymbolAddress((void**)&docH,   g_docH);
    cudaGetSymbolAddress((void**)&docH0,  g_docH0);
    cudaGetSymbolAddress((void**)&hidden, g_hidden);
    cudaGetSymbolAddress((void**)&doc,    g_doc);
    cudaGetSymbolAddress((void**)&t2,     g_t2);
    cudaGetSymbolAddress((void**)&Arp, g_Arp);
    cudaGetSymbolAddress((void**)&Awp, g_Awp);
    cudaGetSymbolAddress((void**)&Aci, g_Aci);
    cudaGetSymbolAddress((void**)&Av,  g_Av);
    cudaGetSymbolAddress((void**)&Xrp, g_Xrp);
    cudaGetSymbolAddress((void**)&Xwp, g_Xwp);
    cudaGetSymbolAddress((void**)&Xci, g_Xci);
    cudaGetSymbolAddress((void**)&Xv,  g_Xv);
    cudaGetSymbolAddress((void**)&Whi, g_Whi);
    cudaGetSymbolAddress((void**)&Wlo, g_Wlo);

    const int gcnGrid = (N + 63) / 64;
    const int docGrid = (D + 63) / 64;

    // ---- pre-split + transpose all weights into bf16x2 hi/lo Wt[n][K/2] ----
    {
        const dim3 tb(32, 8);
        k_wsplit_t<<<dim3(6, 12),  tb>>>(W1,      192, 384, Whi + OFF_W1,  Wlo + OFF_W1);
        k_wsplit_t<<<dim3(6, 12),  tb>>>(W2,      192, 384, Whi + OFF_W2,  Wlo + OFF_W2);
        k_wsplit_t<<<dim3(6, 12),  tb>>>(W3,      192, 384, Whi + OFF_W3,  Wlo + OFF_W3);
        k_wsplit_t<<<dim3(6, 12),  tb>>>(gate_W2, 192, 384, Whi + OFF_GW2, Wlo + OFF_GW2);
        k_wsplit_t<<<dim3(6, 12),  tb>>>(mlp_W1,  192, 384, Whi + OFF_MW1, Wlo + OFF_MW1);
        k_wsplit_t<<<dim3(12, 12), tb>>>(gate_W1, 384, 384, Whi + OFF_GW1, Wlo + OFF_GW1);
        k_wsplit_t<<<dim3(6, 6),   tb>>>(mlp_W2,  192, 192, Whi + OFF_MW2, Wlo + OFF_MW2);
    }

    // ---- build CSR for A and X ----
    k_zero_i32<<<(N + 2 + 255) / 256, 256>>>(Arp, N + 1);
    k_hist    <<<(E + 255) / 256, 256>>>(A_rows, E, Arp);
    k_scan_excl<<<1, 1024>>>(Arp, N, Awp);
    k_scatter <<<(E + 255) / 256, 256>>>(A_rows, A_cols, A_vals, E, Awp, Aci, Av);

    k_zero_i32<<<(D + 2 + 255) / 256, 256>>>(Xrp, D + 1);
    k_hist    <<<(NNZ + 255) / 256, 256>>>(X_rows, NNZ, Xrp);
    k_scan_excl<<<1, 1024>>>(Xrp, D, Xwp);
    k_scatter <<<(NNZ + 255) / 256, 256>>>(X_rows, X_cols, X_vals, NNZ, Xwp, Xci, Xv);

    // ---- 3 residual GCN blocks ----
    k_spmm<<<N, 96>>>(Arp, Aci, Av, emb, buf1);
    k_gemm<HDIM, EPI_LN_GELU><<<gcnGrid, 512>>>(buf1, nullptr, HDIM, HDIM,
        Whi + OFF_W1, Wlo + OFF_W1, nullptr, g1, b1, nullptr, nullptr, nullptr, buf2, N);

    k_spmm<<<N, 96>>>(Arp, Aci, Av, buf2, buf1);
    k_gemm<HDIM, EPI_LN_GELU><<<gcnGrid, 512>>>(buf1, nullptr, HDIM, HDIM,
        Whi + OFF_W2, Wlo + OFF_W2, nullptr, g2, b2, nullptr, nullptr, nullptr, buf2, N);

    k_spmm<<<N, 96>>>(Arp, Aci, Av, buf2, buf1);
    k_gemm<HDIM, EPI_LN_GELU><<<gcnGrid, 512>>>(buf1, nullptr, HDIM, HDIM,
        Whi + OFF_W3, Wlo + OFF_W3, nullptr, g3, b3, nullptr, nullptr, emb, buf2, N);

    // ---- doc aggregation (fused: docH from word_H, docH0 from emb) ----
    k_spmm2<<<D, 96>>>(Xrp, Xci, Xv, buf2, emb, docH, docH0);

    // gate hidden = gelu([docH | docH0] @ gate_W1 + gate_b1)
    k_gemm<HDIM, EPI_GELU><<<docGrid, 512>>>(docH, docH0, 2 * HDIM, HDIM,
        Whi + OFF_GW1, Wlo + OFF_GW1, gate_b1, nullptr, nullptr, nullptr, nullptr, nullptr, hidden, D);

    // gate = sigmoid(hidden @ gate_W2 + gate_b2); doc = gate*docH + (1-gate)*docH0
    k_gemm<HDIM, EPI_GATE><<<docGrid, 512>>>(hidden, nullptr, HDIM, HDIM,
        Whi + OFF_GW2, Wlo + OFF_GW2, gate_b2, nullptr, nullptr, docH, docH0, nullptr, doc, D);

    // mlp1: ln(gelu(doc @ mlp_W1 + mlp_b1))
    k_gemm<HDIM, EPI_GELU_LN><<<docGrid, 512>>>(doc, nullptr, HDIM, HDIM,
        Whi + OFF_MW1, Wlo + OFF_MW1, mlp_b1, mlp_g, mlp_bn, nullptr, nullptr, nullptr, hidden, D);

    // mlp2: gelu(hidden @ mlp_W2 + mlp_b2) -> [D, 192]
    k_gemm<HHALF, EPI_GELU><<<docGrid, 256>>>(hidden, nullptr, HDIM, HDIM,
        Whi + OFF_MW2, Wlo + OFF_MW2, mlp_b2, nullptr, nullptr, nullptr, nullptr, nullptr, t2, D);

    // logits
    k_logits<<<(D + 7) / 8, 256>>>(t2, cls_W, cls_b, out, D);
}

// round 12
// speedup vs baseline: 1.2085x; 1.2085x over previous
#include <cuda_runtime.h>
#include <cuda_fp16.h>
#include <math.h>
#include <stdint.h>

// ---------------- problem constants ----------------
#define HDIM  384
#define HHALF 192
constexpr int   MAXN   = 40000;
constexpr int   MAXD   = 20000;
constexpr int   MAXE   = 800000;
constexpr int   MAXNNZ = 800000;
constexpr float ALPHA  = 0.65f;
constexpr float LN_EPS = 1e-5f;

// weight fp16 pool offsets (u32 units, layout [K/2][NCOLS] f16x2 k-pairs)
constexpr int OFF_W1  = 0;
constexpr int OFF_W2  = 73728;
constexpr int OFF_W3  = 147456;
constexpr int OFF_GW2 = 221184;
constexpr int OFF_MW1 = 294912;
constexpr int OFF_GW1 = 368640;   // K=768 x 384
constexpr int OFF_MW2 = 516096;   // 192 x 192
constexpr int WPOOL   = 552960;

// ---------------- static scratch ----------------
__device__ float g_buf1[(size_t)MAXN * HDIM];
__device__ float g_buf2[(size_t)MAXN * HDIM];
__device__ float g_docH [(size_t)MAXD * HDIM];
__device__ float g_docH0[(size_t)MAXD * HDIM];
__device__ float g_hidden[(size_t)MAXD * HDIM];
__device__ float g_doc  [(size_t)MAXD * HDIM];
__device__ float g_t2   [(size_t)MAXD * HHALF];

__device__ __align__(16) uint32_t g_Wh[WPOOL];

__device__ int   g_Arp[MAXN + 1];
__device__ int   g_Awp[MAXN + 1];
__device__ int   g_Aci[MAXE];
__device__ float g_Av [MAXE];
__device__ int   g_Xrp[MAXD + 1];
__device__ int   g_Xwp[MAXD + 1];
__device__ int   g_Xci[MAXNNZ];
__device__ float g_Xv [MAXNNZ];

// ---------------- helpers ----------------
__device__ __forceinline__ float gelu_exact(float x) {
    return 0.5f * x * (1.0f + erff(x * 0.70710678118654752f));
}
__device__ __forceinline__ float sigmoidf_(float x) {
    return 1.0f / (1.0f + __expf(-x));
}
// pack (x,y) into f16x2 (x -> low half, y -> high half)
__device__ __forceinline__ uint32_t cvth2(float x, float y) {
    __half2 h = __floats2half2_rn(x, y);
    return *reinterpret_cast<uint32_t*>(&h);
}
// split (x,y): hi = f16x2(x,y), lo = f16x2 of residuals
__device__ __forceinline__ void hsplit2(float x, float y, uint32_t& h, uint32_t& l) {
    __half2 hh = __floats2half2_rn(x, y);
    float2 f = __half22float2(hh);
    __half2 ll = __floats2half2_rn(x - f.x, y - f.y);
    h = *reinterpret_cast<uint32_t*>(&hh);
    l = *reinterpret_cast<uint32_t*>(&ll);
}
__device__ __forceinline__ void mma_f16(float* d, const uint32_t* a, const uint32_t* b) {
    asm volatile(
        "mma.sync.aligned.m16n8k16.row.col.f32.f16.f16.f32 "
        "{%0,%1,%2,%3}, {%4,%5,%6,%7}, {%8,%9}, {%0,%1,%2,%3};"
        : "+f"(d[0]), "+f"(d[1]), "+f"(d[2]), "+f"(d[3])
        : "r"(a[0]), "r"(a[1]), "r"(a[2]), "r"(a[3]), "r"(b[0]), "r"(b[1]));
}
__device__ __forceinline__ void fma4(float4& a, float v, const float4& m) {
    a.x = fmaf(v, m.x, a.x);
    a.y = fmaf(v, m.y, a.y);
    a.z = fmaf(v, m.z, a.z);
    a.w = fmaf(v, m.w, a.w);
}

// ---------------- weight fp16 pack: W[K][NC] -> u32[K/2][NC] (f16x2 k-pairs) ----------------
__global__ void k_wpack(const float* __restrict__ W, int KP, int NC,
                        uint32_t* __restrict__ hi) {
    int idx = blockIdx.x * blockDim.x + threadIdx.x;
    if (idx >= KP * NC) return;
    int kp = idx / NC, n = idx - kp * NC;
    float x = W[(size_t)(2 * kp) * NC + n];
    float y = W[(size_t)(2 * kp + 1) * NC + n];
    hi[idx] = cvth2(x, y);
}

// ---------------- CSR build ----------------
__global__ void k_zero_i32(int* p, int n) {
    int i = blockIdx.x * blockDim.x + threadIdx.x;
    if (i < n) p[i] = 0;
}

__global__ void k_hist(const int* __restrict__ rows, int ne, int* __restrict__ cnt) {
    int e = blockIdx.x * blockDim.x + threadIdx.x;
    if (e < ne) atomicAdd(&cnt[rows[e]], 1);
}

__global__ void k_scan_excl(int* __restrict__ data, int n, int* __restrict__ wp) {
    __shared__ int sums[1024];
    int t = threadIdx.x;
    int C = (n + 1023) / 1024;
    int start = t * C;
    int end   = min(start + C, n);

    int s = 0;
    for (int i = start; i < end; i++) s += data[i];
    sums[t] = s;
    __syncthreads();

    for (int off = 1; off < 1024; off <<= 1) {
        int add = (t >= off) ? sums[t - off] : 0;
        __syncthreads();
        sums[t] += add;
        __syncthreads();
    }

    int run = sums[t] - s;
    for (int i = start; i < end; i++) {
        int c = data[i];
        data[i] = run;
        wp[i]   = run;
        run += c;
    }
    if (t == 1023) data[n] = sums[1023];
}

__global__ void k_scatter(const int* __restrict__ rows, const int* __restrict__ cols,
                          const float* __restrict__ vals, int ne,
                          int* __restrict__ wp, int* __restrict__ ci,
                          float* __restrict__ cv) {
    int e = blockIdx.x * blockDim.x + threadIdx.x;
    if (e < ne) {
        int pos = atomicAdd(&wp[rows[e]], 1);
        ci[pos] = cols[e];
        cv[pos] = vals[e];
    }
}

// ---------------- SpMM (CSR gather, float4, unroll-4) ----------------
__global__ void __launch_bounds__(96)
k_spmm(const int* __restrict__ rp, const int* __restrict__ ci,
       const float* __restrict__ cv, const float* __restrict__ M,
       float* __restrict__ out) {
    const int r = blockIdx.x;
    const int t = threadIdx.x;
    const int s = rp[r], e = rp[r + 1];
    const float4* __restrict__ M4 = (const float4*)M;
    float4 acc = make_float4(0.f, 0.f, 0.f, 0.f);

    int j = s;
    for (; j + 4 <= e; j += 4) {
        int   c0 = ci[j],     c1 = ci[j + 1], c2 = ci[j + 2], c3 = ci[j + 3];
        float v0 = cv[j],     v1 = cv[j + 1], v2 = cv[j + 2], v3 = cv[j + 3];
        float4 m0 = M4[(size_t)c0 * 96 + t];
        float4 m1 = M4[(size_t)c1 * 96 + t];
        float4 m2 = M4[(size_t)c2 * 96 + t];
        float4 m3 = M4[(size_t)c3 * 96 + t];
        fma4(acc, v0, m0);
        fma4(acc, v1, m1);
        fma4(acc, v2, m2);
        fma4(acc, v3, m3);
    }
    for (; j < e; j++) {
        float4 m = M4[(size_t)ci[j] * 96 + t];
        fma4(acc, cv[j], m);
    }
    ((float4*)(out + (size_t)r * HDIM))[t] = acc;
}

__global__ void __launch_bounds__(96)
k_spmm2(const int* __restrict__ rp, const int* __restrict__ ci,
        const float* __restrict__ cv,
        const float* __restrict__ Ma, const float* __restrict__ Mb,
        float* __restrict__ outA, float* __restrict__ outB) {
    const int r = blockIdx.x;
    const int t = threadIdx.x;
    const int s = rp[r], e = rp[r + 1];
    const float4* __restrict__ A4 = (const float4*)Ma;
    const float4* __restrict__ B4 = (const float4*)Mb;
    float4 accA = make_float4(0.f, 0.f, 0.f, 0.f);
    float4 accB = make_float4(0.f, 0.f, 0.f, 0.f);

    int j = s;
    for (; j + 2 <= e; j += 2) {
        int   c0 = ci[j],  c1 = ci[j + 1];
        float v0 = cv[j],  v1 = cv[j + 1];
        float4 a0 = A4[(size_t)c0 * 96 + t];
        float4 b0 = B4[(size_t)c0 * 96 + t];
        float4 a1 = A4[(size_t)c1 * 96 + t];
        float4 b1 = B4[(size_t)c1 * 96 + t];
        fma4(accA, v0, a0);
        fma4(accB, v0, b0);
        fma4(accA, v1, a1);
        fma4(accB, v1, b1);
    }
    for (; j < e; j++) {
        int   c = ci[j];
        float v = cv[j];
        float4 a = A4[(size_t)c * 96 + t];
        float4 b = B4[(size_t)c * 96 + t];
        fma4(accA, v, a);
        fma4(accB, v, b);
    }
    ((float4*)(outA + (size_t)r * HDIM))[t] = accA;
    ((float4*)(outB + (size_t)r * HDIM))[t] = accB;
}

// ---------------- fp16 2-pass split tensor-core GEMM with fused epilogues ----------------
// C[M x NCOLS] = epilogue( A[M x K] @ W[K x NCOLS] ), A may be virtual concat [A1|A2].
// W pre-packed fp16 (single image, [K/2][NCOLS] f16x2). A split in-kernel: a = ah + al,
// both fp16. Two passes: ah*bh + al*bh (error dominated by W's fp16 rounding ~2^-12).
// block tile 64 x NCOLS; warp tile 32 x 48 (2x6 m16n8k16); BK=16; register prefetch.
enum { EPI_LN_GELU = 0, EPI_GELU = 1, EPI_GATE = 2, EPI_GELU_LN = 3 };

template <int NCOLS, int EPI>
__global__ void __launch_bounds__(64 * (NCOLS / 48))
k_gemm(const float* __restrict__ A1, const float* __restrict__ A2,
       int K, int K1,
       const uint32_t* __restrict__ Wh,
       const float* __restrict__ bias,
       const float* __restrict__ gw, const float* __restrict__ bw,
       const float* __restrict__ aux1, const float* __restrict__ aux2,
       const float* __restrict__ res,
       float* __restrict__ out, int M) {
    constexpr int NWN     = NCOLS / 48;
    constexpr int THREADS = 64 * NWN;
    constexpr int BM = 64, BK = 16;
    constexpr int MT = 2, NT = 6;
    constexpr int AV4 = BM * BK / 4;              // 256 float4
    constexpr int BU4 = (8 * NCOLS) / 4;          // uint4 per B tile
    constexpr int BITER = (BU4 + THREADS - 1) / THREADS;
    constexpr int BROW = NCOLS + 8;

    __shared__ uint32_t AsH[BM][12], AsL[BM][12];   // k-pairs, stride 12
    __shared__ uint32_t BsH[8][BROW];
    __shared__ float redS[2][32][NWN];
    __shared__ float redQ[2][32][NWN];

    const int tid  = threadIdx.x;
    const int lane = tid & 31;
    const int warp = tid >> 5;
    const int wm = warp & 1;
    const int wn = warp >> 1;
    const int g  = lane >> 2;
    const int t  = lane & 3;
    const int bm0 = blockIdx.x * BM;
    const int NC  = K / BK;

    float acc[MT][NT][4];
#pragma unroll
    for (int mt = 0; mt < MT; mt++)
#pragma unroll
        for (int nt = 0; nt < NT; nt++)
#pragma unroll
            for (int c = 0; c < 4; c++) acc[mt][nt][c] = 0.f;

    float4 pa;
    uint4  pbh[BITER];

    auto gload = [&](int k0) {
        const float* Ab;
        int kc, AW;
        if (k0 < K1) { Ab = A1; kc = k0; AW = K1; }
        else         { Ab = A2; kc = k0 - K1; AW = K - K1; }
        if (tid < AV4) {
            int row = tid >> 2, f4 = tid & 3;
            int grow = bm0 + row;
            if (grow < M)
                pa = *(const float4*)(Ab + (size_t)grow * AW + kc + 4 * f4);
            else
                pa = make_float4(0.f, 0.f, 0.f, 0.f);
        }
        const uint4* bh = (const uint4*)(Wh + (size_t)(k0 / 2) * NCOLS);
#pragma unroll
        for (int i = 0; i < BITER; i++) {
            int idx = tid + i * THREADS;
            if (idx < BU4) pbh[i] = bh[idx];
        }
    };
    auto sstore = [&]() {
        if (tid < AV4) {
            int row = tid >> 2, f4 = tid & 3;
            uint32_t h0, l0, h1, l1;
            hsplit2(pa.x, pa.y, h0, l0);
            hsplit2(pa.z, pa.w, h1, l1);
            AsH[row][2 * f4]     = h0;
            AsH[row][2 * f4 + 1] = h1;
            AsL[row][2 * f4]     = l0;
            AsL[row][2 * f4 + 1] = l1;
        }
#pragma unroll
        for (int i = 0; i < BITER; i++) {
            int idx = tid + i * THREADS;
            if (idx < BU4) {
                int off = 4 * idx;
                int r = off / NCOLS, n = off - r * NCOLS;
                *(uint4*)&BsH[r][n] = pbh[i];
            }
        }
    };

    gload(0);
    sstore();
    __syncthreads();

    for (int c = 0; c < NC; c++) {
        if (c + 1 < NC) gload((c + 1) * BK);

        // load fragments
        uint32_t ah[MT][4], al[MT][4], bh[NT][2];
#pragma unroll
        for (int mt = 0; mt < MT; mt++) {
            int r0 = wm * 32 + mt * 16;
            ah[mt][0] = AsH[r0 + g][t];
            ah[mt][1] = AsH[r0 + g + 8][t];
            ah[mt][2] = AsH[r0 + g][t + 4];
            ah[mt][3] = AsH[r0 + g + 8][t + 4];
            al[mt][0] = AsL[r0 + g][t];
            al[mt][1] = AsL[r0 + g + 8][t];
            al[mt][2] = AsL[r0 + g][t + 4];
            al[mt][3] = AsL[r0 + g + 8][t + 4];
        }
#pragma unroll
        for (int nt = 0; nt < NT; nt++) {
            int n0 = wn * 48 + nt * 8 + g;
            bh[nt][0] = BsH[t][n0];
            bh[nt][1] = BsH[t + 4][n0];
        }

        // pass 1: ah * bh  (12 independent accumulators)
#pragma unroll
        for (int nt = 0; nt < NT; nt++)
#pragma unroll
            for (int mt = 0; mt < MT; mt++)
                mma_f16(acc[mt][nt], ah[mt], bh[nt]);
        // pass 2: al * bh
#pragma unroll
        for (int nt = 0; nt < NT; nt++)
#pragma unroll
            for (int mt = 0; mt < MT; mt++)
                mma_f16(acc[mt][nt], al[mt], bh[nt]);

        __syncthreads();
        if (c + 1 < NC) {
            sstore();
            __syncthreads();
        }
    }

    // -------- epilogues --------
    // acc[mt][nt][c]: row = wm*32 + mt*16 + 8*(c>>1) + g ; col = wn*48 + nt*8 + 2*t + (c&1)
    if constexpr (EPI == EPI_GELU) {
#pragma unroll
        for (int mt = 0; mt < MT; mt++)
#pragma unroll
            for (int d = 0; d < 2; d++) {
                int grow = bm0 + wm * 32 + mt * 16 + 8 * d + g;
                if (grow >= M) continue;
#pragma unroll
                for (int nt = 0; nt < NT; nt++) {
                    int col = wn * 48 + nt * 8 + 2 * t;
                    float v0 = acc[mt][nt][2 * d]     + (bias ? bias[col]     : 0.f);
                    float v1 = acc[mt][nt][2 * d + 1] + (bias ? bias[col + 1] : 0.f);
                    *(float2*)&out[(size_t)grow * NCOLS + col] =
                        make_float2(gelu_exact(v0), gelu_exact(v1));
                }
            }
    } else if constexpr (EPI == EPI_GATE) {
#pragma unroll
        for (int mt = 0; mt < MT; mt++)
#pragma unroll
            for (int d = 0; d < 2; d++) {
                int grow = bm0 + wm * 32 + mt * 16 + 8 * d + g;
                if (grow >= M) continue;
#pragma unroll
                for (int nt = 0; nt < NT; nt++) {
                    int col = wn * 48 + nt * 8 + 2 * t;
                    size_t idx = (size_t)grow * NCOLS + col;
                    float s0 = sigmoidf_(acc[mt][nt][2 * d]     + bias[col]);
                    float s1 = sigmoidf_(acc[mt][nt][2 * d + 1] + bias[col + 1]);
                    float2 h1 = *(const float2*)&aux1[idx];
                    float2 h0 = *(const float2*)&aux2[idx];
                    *(float2*)&out[idx] = make_float2(
                        s0 * h1.x + (1.f - s0) * h0.x,
                        s1 * h1.y + (1.f - s1) * h0.y);
                }
            }
    } else {
        float sm_[MT][2], sq_[MT][2];
#pragma unroll
        for (int mt = 0; mt < MT; mt++)
#pragma unroll
            for (int d = 0; d < 2; d++) { sm_[mt][d] = 0.f; sq_[mt][d] = 0.f; }

#pragma unroll
        for (int mt = 0; mt < MT; mt++)
#pragma unroll
            for (int nt = 0; nt < NT; nt++) {
                int col = wn * 48 + nt * 8 + 2 * t;
#pragma unroll
                for (int d = 0; d < 2; d++) {
                    float v0 = acc[mt][nt][2 * d];
                    float v1 = acc[mt][nt][2 * d + 1];
                    if constexpr (EPI == EPI_GELU_LN) {
                        v0 = gelu_exact(v0 + bias[col]);
                        v1 = gelu_exact(v1 + bias[col + 1]);
                        acc[mt][nt][2 * d] = v0;
                        acc[mt][nt][2 * d + 1] = v1;
                    }
                    sm_[mt][d] += v0 + v1;
                    sq_[mt][d] += v0 * v0 + v1 * v1;
                }
            }
#pragma unroll
        for (int mt = 0; mt < MT; mt++)
#pragma unroll
            for (int d = 0; d < 2; d++) {
                float s = sm_[mt][d], q = sq_[mt][d];
                s += __shfl_xor_sync(0xffffffffu, s, 1);
                q += __shfl_xor_sync(0xffffffffu, q, 1);
                s += __shfl_xor_sync(0xffffffffu, s, 2);
                q += __shfl_xor_sync(0xffffffffu, q, 2);
                sm_[mt][d] = s; sq_[mt][d] = q;
            }
        if (t == 0) {
#pragma unroll
            for (int mt = 0; mt < MT; mt++)
#pragma unroll
                for (int d = 0; d < 2; d++) {
                    int rr = mt * 16 + 8 * d + g;
                    redS[wm][rr][wn] = sm_[mt][d];
                    redQ[wm][rr][wn] = sq_[mt][d];
                }
        }
        __syncthreads();
#pragma unroll
        for (int mt = 0; mt < MT; mt++)
#pragma unroll
            for (int d = 0; d < 2; d++) {
                int rr = mt * 16 + 8 * d + g;
                float S = 0.f, Q = 0.f;
#pragma unroll
                for (int w = 0; w < NWN; w++) { S += redS[wm][rr][w]; Q += redQ[wm][rr][w]; }
                float mean = S * (1.0f / NCOLS);
                float var  = Q * (1.0f / NCOLS) - mean * mean;
                float rstd = rsqrtf(var + LN_EPS);
                int grow = bm0 + wm * 32 + rr;
                if (grow >= M) continue;
#pragma unroll
                for (int nt = 0; nt < NT; nt++) {
                    int col = wn * 48 + nt * 8 + 2 * t;
                    float nv0 = (acc[mt][nt][2 * d]     - mean) * rstd * gw[col]     + bw[col];
                    float nv1 = (acc[mt][nt][2 * d + 1] - mean) * rstd * gw[col + 1] + bw[col + 1];
                    float o0, o1;
                    if constexpr (EPI == EPI_LN_GELU) {
                        o0 = gelu_exact(nv0);
                        o1 = gelu_exact(nv1);
                        if (res) {
                            float2 rv = *(const float2*)&res[(size_t)grow * NCOLS + col];
                            o0 = (1.f - ALPHA) * rv.x + ALPHA * o0;
                            o1 = (1.f - ALPHA) * rv.y + ALPHA * o1;
                        }
                    } else {
                        o0 = nv0; o1 = nv1;
                    }
                    *(float2*)&out[(size_t)grow * NCOLS + col] = make_float2(o0, o1);
                }
            }
    }
}

// ---------------- final tiny classifier ----------------
__global__ void k_logits(const float* __restrict__ t2, const float* __restrict__ clsW,
                         const float* __restrict__ clsb, float* __restrict__ out, int D) {
    int warp = (blockIdx.x * blockDim.x + threadIdx.x) >> 5;
    int lane = threadIdx.x & 31;
    if (warp >= D) return;
    const float* r = t2 + (size_t)warp * HHALF;
    float a0 = 0.f, a1 = 0.f;
    for (int k = lane; k < HHALF; k += 32) {
        float x = r[k];
        a0 = fmaf(x, clsW[2 * k],     a0);
        a1 = fmaf(x, clsW[2 * k + 1], a1);
    }
    for (int off = 16; off > 0; off >>= 1) {
        a0 += __shfl_down_sync(0xffffffffu, a0, off);
        a1 += __shfl_down_sync(0xffffffffu, a1, off);
    }
    if (lane == 0) {
        out[2 * warp]     = a0 + clsb[0];
        out[2 * warp + 1] = a1 + clsb[1];
    }
}

// ---------------- launch ----------------
extern "C" void kernel_launch(void* const* d_in, const int* in_sizes, int n_in,
                              void* d_out, int out_size) {
    const int*   A_rows  = (const int*)  d_in[0];
    const int*   A_cols  = (const int*)  d_in[1];
    const float* A_vals  = (const float*)d_in[2];
    const int*   X_rows  = (const int*)  d_in[3];
    const int*   X_cols  = (const int*)  d_in[4];
    const float* X_vals  = (const float*)d_in[5];
    const float* emb     = (const float*)d_in[7];
    const float* W1      = (const float*)d_in[8];
    const float* W2      = (const float*)d_in[9];
    const float* W3      = (const float*)d_in[10];
    const float* g1      = (const float*)d_in[11];
    const float* b1      = (const float*)d_in[12];
    const float* g2      = (const float*)d_in[13];
    const float* b2      = (const float*)d_in[14];
    const float* g3      = (const float*)d_in[15];
    const float* b3      = (const float*)d_in[16];
    const float* mlp_W1  = (const float*)d_in[17];
    const float* mlp_b1  = (const float*)d_in[18];
    const float* mlp_g   = (const float*)d_in[19];
    const float* mlp_bn  = (const float*)d_in[20];
    const float* mlp_W2  = (const float*)d_in[21];
    const float* mlp_b2  = (const float*)d_in[22];
    const float* cls_W   = (const float*)d_in[23];
    const float* cls_b   = (const float*)d_in[24];
    const float* gate_W1 = (const float*)d_in[25];
    const float* gate_b1 = (const float*)d_in[26];
    const float* gate_W2 = (const float*)d_in[27];
    const float* gate_b2 = (const float*)d_in[28];

    const int E   = in_sizes[0];
    const int NNZ = in_sizes[3];
    const int N   = in_sizes[7] / HDIM;
    const int D   = out_size / 2;
    float* out = (float*)d_out;

    float *buf1, *buf2, *docH, *docH0, *hidden, *doc, *t2;
    int *Arp, *Awp, *Aci, *Xrp, *Xwp, *Xci;
    float *Av, *Xv;
    uint32_t *Wh;
    cudaGetSymbolAddress((void**)&buf1,   g_buf1);
    cudaGetSymbolAddress((void**)&buf2,   g_buf2);
    cudaGetSymbolAddress((void**)&docH,   g_docH);
    cudaGetSymbolAddress((void**)&docH0,  g_docH0);
    cudaGetSymbolAddress((void**)&hidden, g_hidden);
    cudaGetSymbolAddress((void**)&doc,    g_doc);
    cudaGetSymbolAddress((void**)&t2,     g_t2);
    cudaGetSymbolAddress((void**)&Arp, g_Arp);
    cudaGetSymbolAddress((void**)&Awp, g_Awp);
    cudaGetSymbolAddress((void**)&Aci, g_Aci);
    cudaGetSymbolAddress((void**)&Av,  g_Av);
    cudaGetSymbolAddress((void**)&Xrp, g_Xrp);
    cudaGetSymbolAddress((void**)&Xwp, g_Xwp);
    cudaGetSymbolAddress((void**)&Xci, g_Xci);
    cudaGetSymbolAddress((void**)&Xv,  g_Xv);
    cudaGetSymbolAddress((void**)&Wh,  g_Wh);

    const int gcnGrid = (N + 63) / 64;
    const int docGrid = (D + 63) / 64;

    // ---- pre-pack all weights to fp16 (k-pair-major) ----
    {
        const int n384 = 192 * 384;
        k_wpack<<<(n384 + 255) / 256, 256>>>(W1,      192, 384, Wh + OFF_W1);
        k_wpack<<<(n384 + 255) / 256, 256>>>(W2,      192, 384, Wh + OFF_W2);
        k_wpack<<<(n384 + 255) / 256, 256>>>(W3,      192, 384, Wh + OFF_W3);
        k_wpack<<<(n384 + 255) / 256, 256>>>(gate_W2, 192, 384, Wh + OFF_GW2);
        k_wpack<<<(n384 + 255) / 256, 256>>>(mlp_W1,  192, 384, Wh + OFF_MW1);
        const int ngw1 = 384 * 384;
        k_wpack<<<(ngw1 + 255) / 256, 256>>>(gate_W1, 384, 384, Wh + OFF_GW1);
        k_wpack<<<(192 * 192 + 255) / 256, 256>>>(mlp_W2, 192, 192, Wh + OFF_MW2);
    }

    // ---- build CSR for A and X ----
    k_zero_i32<<<(N + 2 + 255) / 256, 256>>>(Arp, N + 1);
    k_hist    <<<(E + 255) / 256, 256>>>(A_rows, E, Arp);
    k_scan_excl<<<1, 1024>>>(Arp, N, Awp);
    k_scatter <<<(E + 255) / 256, 256>>>(A_rows, A_cols, A_vals, E, Awp, Aci, Av);

    k_zero_i32<<<(D + 2 + 255) / 256, 256>>>(Xrp, D + 1);
    k_hist    <<<(NNZ + 255) / 256, 256>>>(X_rows, NNZ, Xrp);
    k_scan_excl<<<1, 1024>>>(Xrp, D, Xwp);
    k_scatter <<<(NNZ + 255) / 256, 256>>>(X_rows, X_cols, X_vals, NNZ, Xwp, Xci, Xv);

    // ---- 3 residual GCN blocks ----
    k_spmm<<<N, 96>>>(Arp, Aci, Av, emb, buf1);
    k_gemm<HDIM, EPI_LN_GELU><<<gcnGrid, 512>>>(buf1, nullptr, HDIM, HDIM,
        Wh + OFF_W1, nullptr, g1, b1, nullptr, nullptr, nullptr, buf2, N);

    k_spmm<<<N, 96>>>(Arp, Aci, Av, buf2, buf1);
    k_gemm<HDIM, EPI_LN_GELU><<<gcnGrid, 512>>>(buf1, nullptr, HDIM, HDIM,
        Wh + OFF_W2, nullptr, g2, b2, nullptr, nullptr, nullptr, buf2, N);

    k_spmm<<<N, 96>>>(Arp, Aci, Av, buf2, buf1);
    k_gemm<HDIM, EPI_LN_GELU><<<gcnGrid, 512>>>(buf1, nullptr, HDIM, HDIM,
        Wh + OFF_W3, nullptr, g3, b3, nullptr, nullptr, emb, buf2, N);

    // ---- doc aggregation (fused: docH from word_H, docH0 from emb) ----
    k_spmm2<<<D, 96>>>(Xrp, Xci, Xv, buf2, emb, docH, docH0);

    // gate hidden = gelu([docH | docH0] @ gate_W1 + gate_b1)
    k_gemm<HDIM, EPI_GELU><<<docGrid, 512>>>(docH, docH0, 2 * HDIM, HDIM,
        Wh + OFF_GW1, gate_b1, nullptr, nullptr, nullptr, nullptr, nullptr, hidden, D);

    // gate = sigmoid(hidden @ gate_W2 + gate_b2); doc = gate*docH + (1-gate)*docH0
    k_gemm<HDIM, EPI_GATE><<<docGrid, 512>>>(hidden, nullptr, HDIM, HDIM,
        Wh + OFF_GW2, gate_b2, nullptr, nullptr, docH, docH0, nullptr, doc, D);

    // mlp1: ln(gelu(doc @ mlp_W1 + mlp_b1))
    k_gemm<HDIM, EPI_GELU_LN><<<docGrid, 512>>>(doc, nullptr, HDIM, HDIM,
        Wh + OFF_MW1, mlp_b1, mlp_g, mlp_bn, nullptr, nullptr, nullptr, hidden, D);

    // mlp2: gelu(hidden @ mlp_W2 + mlp_b2) -> [D, 192]
    k_gemm<HHALF, EPI_GELU><<<docGrid, 256>>>(hidden, nullptr, HDIM, HDIM,
        Wh + OFF_MW2, mlp_b2, nullptr, nullptr, nullptr, nullptr, nullptr, t2, D);

    // logits
    k_logits<<<(D + 7) / 8, 256>>>(t2, cls_W, cls_b, out, D);
}

// round 13
// speedup vs baseline: 1.2349x; 1.0218x over previous
#include <cuda_runtime.h>
#include <cuda_fp16.h>
#include <math.h>
#include <stdint.h>

// ---------------- problem constants ----------------
#define HDIM  384
#define HHALF 192
constexpr int   MAXN   = 40000;
constexpr int   MAXD   = 20000;
constexpr int   MAXE   = 800000;
constexpr int   MAXNNZ = 800000;
constexpr float ALPHA  = 0.65f;
constexpr float LN_EPS = 1e-5f;

// weight fp16 pool offsets (u32 units, layout [K/2][NCOLS] f16x2 k-pairs)
constexpr int OFF_W1  = 0;
constexpr int OFF_W2  = 73728;
constexpr int OFF_W3  = 147456;
constexpr int OFF_GW2 = 221184;
constexpr int OFF_MW1 = 294912;
constexpr int OFF_GW1 = 368640;   // K=768 x 384
constexpr int OFF_MW2 = 516096;   // 192 x 192
constexpr int WPOOL   = 552960;

// ---------------- static scratch ----------------
__device__ float g_buf1[(size_t)MAXN * HDIM];
__device__ float g_buf2[(size_t)MAXN * HDIM];
__device__ float g_docH [(size_t)MAXD * HDIM];
__device__ float g_docH0[(size_t)MAXD * HDIM];
__device__ float g_hidden[(size_t)MAXD * HDIM];
__device__ float g_doc  [(size_t)MAXD * HDIM];
__device__ float g_t2   [(size_t)MAXD * HHALF];

__device__ __align__(16) uint32_t g_Wh[WPOOL];

__device__ int   g_Arp[MAXN + 1];
__device__ int   g_Awp[MAXN + 1];
__device__ int   g_Aci[MAXE];
__device__ float g_Av [MAXE];
__device__ int   g_Xrp[MAXD + 1];
__device__ int   g_Xwp[MAXD + 1];
__device__ int   g_Xci[MAXNNZ];
__device__ float g_Xv [MAXNNZ];

// ---------------- helpers ----------------
__device__ __forceinline__ float gelu_exact(float x) {
    return 0.5f * x * (1.0f + erff(x * 0.70710678118654752f));
}
__device__ __forceinline__ float sigmoidf_(float x) {
    return 1.0f / (1.0f + __expf(-x));
}
__device__ __forceinline__ uint32_t cvth2(float x, float y) {
    __half2 h = __floats2half2_rn(x, y);
    return *reinterpret_cast<uint32_t*>(&h);
}
// split (x,y): hi = f16x2(x,y), lo = f16x2 of residuals
__device__ __forceinline__ void hsplit2(float x, float y, uint32_t& h, uint32_t& l) {
    __half2 hh = __floats2half2_rn(x, y);
    float2 f = __half22float2(hh);
    __half2 ll = __floats2half2_rn(x - f.x, y - f.y);
    h = *reinterpret_cast<uint32_t*>(&hh);
    l = *reinterpret_cast<uint32_t*>(&ll);
}
__device__ __forceinline__ void mma_f16(float* d, const uint32_t* a, const uint32_t* b) {
    asm volatile(
        "mma.sync.aligned.m16n8k16.row.col.f32.f16.f16.f32 "
        "{%0,%1,%2,%3}, {%4,%5,%6,%7}, {%8,%9}, {%0,%1,%2,%3};"
        : "+f"(d[0]), "+f"(d[1]), "+f"(d[2]), "+f"(d[3])
        : "r"(a[0]), "r"(a[1]), "r"(a[2]), "r"(a[3]), "r"(b[0]), "r"(b[1]));
}
__device__ __forceinline__ void fma4(float4& a, float v, const float4& m) {
    a.x = fmaf(v, m.x, a.x);
    a.y = fmaf(v, m.y, a.y);
    a.z = fmaf(v, m.z, a.z);
    a.w = fmaf(v, m.w, a.w);
}

// ---------------- weight fp16 pack: W[K][NC] -> u32[K/2][NC] (f16x2 k-pairs) ----------------
__global__ void k_wpack(const float* __restrict__ W, int KP, int NC,
                        uint32_t* __restrict__ hi) {
    int idx = blockIdx.x * blockDim.x + threadIdx.x;
    if (idx >= KP * NC) return;
    int kp = idx / NC, n = idx - kp * NC;
    float x = W[(size_t)(2 * kp) * NC + n];
    float y = W[(size_t)(2 * kp + 1) * NC + n];
    hi[idx] = cvth2(x, y);
}

// ---------------- CSR build ----------------
__global__ void k_zero_i32(int* p, int n) {
    int i = blockIdx.x * blockDim.x + threadIdx.x;
    if (i < n) p[i] = 0;
}

__global__ void k_hist(const int* __restrict__ rows, int ne, int* __restrict__ cnt) {
    int e = blockIdx.x * blockDim.x + threadIdx.x;
    if (e < ne) atomicAdd(&cnt[rows[e]], 1);
}

__global__ void k_scan_excl(int* __restrict__ data, int n, int* __restrict__ wp) {
    __shared__ int sums[1024];
    int t = threadIdx.x;
    int C = (n + 1023) / 1024;
    int start = t * C;
    int end   = min(start + C, n);

    int s = 0;
    for (int i = start; i < end; i++) s += data[i];
    sums[t] = s;
    __syncthreads();

    for (int off = 1; off < 1024; off <<= 1) {
        int add = (t >= off) ? sums[t - off] : 0;
        __syncthreads();
        sums[t] += add;
        __syncthreads();
    }

    int run = sums[t] - s;
    for (int i = start; i < end; i++) {
        int c = data[i];
        data[i] = run;
        wp[i]   = run;
        run += c;
    }
    if (t == 1023) data[n] = sums[1023];
}

__global__ void k_scatter(const int* __restrict__ rows, const int* __restrict__ cols,
                          const float* __restrict__ vals, int ne,
                          int* __restrict__ wp, int* __restrict__ ci,
                          float* __restrict__ cv) {
    int e = blockIdx.x * blockDim.x + threadIdx.x;
    if (e < ne) {
        int pos = atomicAdd(&wp[rows[e]], 1);
        ci[pos] = cols[e];
        cv[pos] = vals[e];
    }
}

// ---------------- SpMM (CSR gather, float4, unroll-4) ----------------
__global__ void __launch_bounds__(96)
k_spmm(const int* __restrict__ rp, const int* __restrict__ ci,
       const float* __restrict__ cv, const float* __restrict__ M,
       float* __restrict__ out) {
    const int r = blockIdx.x;
    const int t = threadIdx.x;
    const int s = rp[r], e = rp[r + 1];
    const float4* __restrict__ M4 = (const float4*)M;
    float4 acc = make_float4(0.f, 0.f, 0.f, 0.f);

    int j = s;
    for (; j + 4 <= e; j += 4) {
        int   c0 = ci[j],     c1 = ci[j + 1], c2 = ci[j + 2], c3 = ci[j + 3];
        float v0 = cv[j],     v1 = cv[j + 1], v2 = cv[j + 2], v3 = cv[j + 3];
        float4 m0 = M4[(size_t)c0 * 96 + t];
        float4 m1 = M4[(size_t)c1 * 96 + t];
        float4 m2 = M4[(size_t)c2 * 96 + t];
        float4 m3 = M4[(size_t)c3 * 96 + t];
        fma4(acc, v0, m0);
        fma4(acc, v1, m1);
        fma4(acc, v2, m2);
        fma4(acc, v3, m3);
    }
    for (; j < e; j++) {
        float4 m = M4[(size_t)ci[j] * 96 + t];
        fma4(acc, cv[j], m);
    }
    ((float4*)(out + (size_t)r * HDIM))[t] = acc;
}

__global__ void __launch_bounds__(96)
k_spmm2(const int* __restrict__ rp, const int* __restrict__ ci,
        const float* __restrict__ cv,
        const float* __restrict__ Ma, const float* __restrict__ Mb,
        float* __restrict__ outA, float* __restrict__ outB) {
    const int r = blockIdx.x;
    const int t = threadIdx.x;
    const int s = rp[r], e = rp[r + 1];
    const float4* __restrict__ A4 = (const float4*)Ma;
    const float4* __restrict__ B4 = (const float4*)Mb;
    float4 accA = make_float4(0.f, 0.f, 0.f, 0.f);
    float4 accB = make_float4(0.f, 0.f, 0.f, 0.f);

    int j = s;
    for (; j + 2 <= e; j += 2) {
        int   c0 = ci[j],  c1 = ci[j + 1];
        float v0 = cv[j],  v1 = cv[j + 1];
        float4 a0 = A4[(size_t)c0 * 96 + t];
        float4 b0 = B4[(size_t)c0 * 96 + t];
        float4 a1 = A4[(size_t)c1 * 96 + t];
        float4 b1 = B4[(size_t)c1 * 96 + t];
        fma4(accA, v0, a0);
        fma4(accB, v0, b0);
        fma4(accA, v1, a1);
        fma4(accB, v1, b1);
    }
    for (; j < e; j++) {
        int   c = ci[j];
        float v = cv[j];
        float4 a = A4[(size_t)c * 96 + t];
        float4 b = B4[(size_t)c * 96 + t];
        fma4(accA, v, a);
        fma4(accB, v, b);
    }
    ((float4*)(outA + (size_t)r * HDIM))[t] = accA;
    ((float4*)(outB + (size_t)r * HDIM))[t] = accB;
}

// ---------------- fp16 split tensor-core GEMM with fused epilogues ----------------
// C[M x NCOLS] = epilogue( A[M x K] @ W[K x NCOLS] ), A may be virtual concat [A1|A2].
// W pre-packed fp16 ([K/2][NCOLS] f16x2).
// PASSES=2: A split a=ah+al (exact), compute ah*bh + al*bh (A-error ~2^-22).
// PASSES=1: A rounded to fp16, single pass (A-error ~2^-12; used for late doc stage).
// block tile 64 x NCOLS; warp tile 32 x 48 (2x6 m16n8k16); BK=16; register prefetch.
enum { EPI_LN_GELU = 0, EPI_GELU = 1, EPI_GATE = 2, EPI_GELU_LN = 3 };

template <int NCOLS, int EPI, int PASSES>
__global__ void __launch_bounds__(64 * (NCOLS / 48))
k_gemm(const float* __restrict__ A1, const float* __restrict__ A2,
       int K, int K1,
       const uint32_t* __restrict__ Wh,
       const float* __restrict__ bias,
       const float* __restrict__ gw, const float* __restrict__ bw,
       const float* __restrict__ aux1, const float* __restrict__ aux2,
       const float* __restrict__ res,
       float* __restrict__ out, int M) {
    constexpr int NWN     = NCOLS / 48;
    constexpr int THREADS = 64 * NWN;
    constexpr int BM = 64, BK = 16;
    constexpr int MT = 2, NT = 6;
    constexpr int AV4 = BM * BK / 4;              // 256 float4
    constexpr int BU4 = (8 * NCOLS) / 4;          // uint4 per B tile
    constexpr int BITER = (BU4 + THREADS - 1) / THREADS;
    constexpr int BROW = NCOLS + 8;

    __shared__ uint32_t AsH[BM][12];              // k-pairs, stride 12
    __shared__ uint32_t AsL[PASSES == 2 ? BM : 1][12];
    __shared__ uint32_t BsH[8][BROW];
    __shared__ float redS[2][32][NWN];
    __shared__ float redQ[2][32][NWN];

    const int tid  = threadIdx.x;
    const int lane = tid & 31;
    const int warp = tid >> 5;
    const int wm = warp & 1;
    const int wn = warp >> 1;
    const int g  = lane >> 2;
    const int t  = lane & 3;
    const int bm0 = blockIdx.x * BM;
    const int NC  = K / BK;

    float acc[MT][NT][4];
#pragma unroll
    for (int mt = 0; mt < MT; mt++)
#pragma unroll
        for (int nt = 0; nt < NT; nt++)
#pragma unroll
            for (int c = 0; c < 4; c++) acc[mt][nt][c] = 0.f;

    float4 pa;
    uint4  pbh[BITER];

    auto gload = [&](int k0) {
        const float* Ab;
        int kc, AW;
        if (k0 < K1) { Ab = A1; kc = k0; AW = K1; }
        else         { Ab = A2; kc = k0 - K1; AW = K - K1; }
        if (tid < AV4) {
            int row = tid >> 2, f4 = tid & 3;
            int grow = bm0 + row;
            if (grow < M)
                pa = *(const float4*)(Ab + (size_t)grow * AW + kc + 4 * f4);
            else
                pa = make_float4(0.f, 0.f, 0.f, 0.f);
        }
        const uint4* bh = (const uint4*)(Wh + (size_t)(k0 / 2) * NCOLS);
#pragma unroll
        for (int i = 0; i < BITER; i++) {
            int idx = tid + i * THREADS;
            if (idx < BU4) pbh[i] = bh[idx];
        }
    };
    auto sstore = [&]() {
        if (tid < AV4) {
            int row = tid >> 2, f4 = tid & 3;
            if constexpr (PASSES == 2) {
                uint32_t h0, l0, h1, l1;
                hsplit2(pa.x, pa.y, h0, l0);
                hsplit2(pa.z, pa.w, h1, l1);
                AsH[row][2 * f4]     = h0;
                AsH[row][2 * f4 + 1] = h1;
                AsL[row][2 * f4]     = l0;
                AsL[row][2 * f4 + 1] = l1;
            } else {
                AsH[row][2 * f4]     = cvth2(pa.x, pa.y);
                AsH[row][2 * f4 + 1] = cvth2(pa.z, pa.w);
            }
        }
#pragma unroll
        for (int i = 0; i < BITER; i++) {
            int idx = tid + i * THREADS;
            if (idx < BU4) {
                int off = 4 * idx;
                int r = off / NCOLS, n = off - r * NCOLS;
                *(uint4*)&BsH[r][n] = pbh[i];
            }
        }
    };

    gload(0);
    sstore();
    __syncthreads();

    for (int c = 0; c < NC; c++) {
        if (c + 1 < NC) gload((c + 1) * BK);

        // load fragments
        uint32_t ah[MT][4], bh[NT][2];
#pragma unroll
        for (int mt = 0; mt < MT; mt++) {
            int r0 = wm * 32 + mt * 16;
            ah[mt][0] = AsH[r0 + g][t];
            ah[mt][1] = AsH[r0 + g + 8][t];
            ah[mt][2] = AsH[r0 + g][t + 4];
            ah[mt][3] = AsH[r0 + g + 8][t + 4];
        }
#pragma unroll
        for (int nt = 0; nt < NT; nt++) {
            int n0 = wn * 48 + nt * 8 + g;
            bh[nt][0] = BsH[t][n0];
            bh[nt][1] = BsH[t + 4][n0];
        }

        // pass 1: ah * bh
#pragma unroll
        for (int nt = 0; nt < NT; nt++)
#pragma unroll
            for (int mt = 0; mt < MT; mt++)
                mma_f16(acc[mt][nt], ah[mt], bh[nt]);

        if constexpr (PASSES == 2) {
            uint32_t al[MT][4];
#pragma unroll
            for (int mt = 0; mt < MT; mt++) {
                int r0 = wm * 32 + mt * 16;
                al[mt][0] = AsL[r0 + g][t];
                al[mt][1] = AsL[r0 + g + 8][t];
                al[mt][2] = AsL[r0 + g][t + 4];
                al[mt][3] = AsL[r0 + g + 8][t + 4];
            }
#pragma unroll
            for (int nt = 0; nt < NT; nt++)
#pragma unroll
                for (int mt = 0; mt < MT; mt++)
                    mma_f16(acc[mt][nt], al[mt], bh[nt]);
        }

        __syncthreads();
        if (c + 1 < NC) {
            sstore();
            __syncthreads();
        }
    }

    // -------- epilogues --------
    // acc[mt][nt][c]: row = wm*32 + mt*16 + 8*(c>>1) + g ; col = wn*48 + nt*8 + 2*t + (c&1)
    if constexpr (EPI == EPI_GELU) {
#pragma unroll
        for (int mt = 0; mt < MT; mt++)
#pragma unroll
            for (int d = 0; d < 2; d++) {
                int grow = bm0 + wm * 32 + mt * 16 + 8 * d + g;
                if (grow >= M) continue;
#pragma unroll
                for (int nt = 0; nt < NT; nt++) {
                    int col = wn * 48 + nt * 8 + 2 * t;
                    float v0 = acc[mt][nt][2 * d]     + (bias ? bias[col]     : 0.f);
                    float v1 = acc[mt][nt][2 * d + 1] + (bias ? bias[col + 1] : 0.f);
                    *(float2*)&out[(size_t)grow * NCOLS + col] =
                        make_float2(gelu_exact(v0), gelu_exact(v1));
                }
            }
    } else if constexpr (EPI == EPI_GATE) {
#pragma unroll
        for (int mt = 0; mt < MT; mt++)
#pragma unroll
            for (int d = 0; d < 2; d++) {
                int grow = bm0 + wm * 32 + mt * 16 + 8 * d + g;
                if (grow >= M) continue;
#pragma unroll
                for (int nt = 0; nt < NT; nt++) {
                    int col = wn * 48 + nt * 8 + 2 * t;
                    size_t idx = (size_t)grow * NCOLS + col;
                    float s0 = sigmoidf_(acc[mt][nt][2 * d]     + bias[col]);
                    float s1 = sigmoidf_(acc[mt][nt][2 * d + 1] + bias[col + 1]);
                    float2 h1 = *(const float2*)&aux1[idx];
                    float2 h0 = *(const float2*)&aux2[idx];
                    *(float2*)&out[idx] = make_float2(
                        s0 * h1.x + (1.f - s0) * h0.x,
                        s1 * h1.y + (1.f - s1) * h0.y);
                }
            }
    } else {
        float sm_[MT][2], sq_[MT][2];
#pragma unroll
        for (int mt = 0; mt < MT; mt++)
#pragma unroll
            for (int d = 0; d < 2; d++) { sm_[mt][d] = 0.f; sq_[mt][d] = 0.f; }

#pragma unroll
        for (int mt = 0; mt < MT; mt++)
#pragma unroll
            for (int nt = 0; nt < NT; nt++) {
                int col = wn * 48 + nt * 8 + 2 * t;
#pragma unroll
                for (int d = 0; d < 2; d++) {
                    float v0 = acc[mt][nt][2 * d];
                    float v1 = acc[mt][nt][2 * d + 1];
                    if constexpr (EPI == EPI_GELU_LN) {
                        v0 = gelu_exact(v0 + bias[col]);
                        v1 = gelu_exact(v1 + bias[col + 1]);
                        acc[mt][nt][2 * d] = v0;
                        acc[mt][nt][2 * d + 1] = v1;
                    }
                    sm_[mt][d] += v0 + v1;
                    sq_[mt][d] += v0 * v0 + v1 * v1;
                }
            }
#pragma unroll
        for (int mt = 0; mt < MT; mt++)
#pragma unroll
            for (int d = 0; d < 2; d++) {
                float s = sm_[mt][d], q = sq_[mt][d];
                s += __shfl_xor_sync(0xffffffffu, s, 1);
                q += __shfl_xor_sync(0xffffffffu, q, 1);
                s += __shfl_xor_sync(0xffffffffu, s, 2);
                q += __shfl_xor_sync(0xffffffffu, q, 2);
                sm_[mt][d] = s; sq_[mt][d] = q;
            }
        if (t == 0) {
#pragma unroll
            for (int mt = 0; mt < MT; mt++)
#pragma unroll
                for (int d = 0; d < 2; d++) {
                    int rr = mt * 16 + 8 * d + g;
                    redS[wm][rr][wn] = sm_[mt][d];
                    redQ[wm][rr][wn] = sq_[mt][d];
                }
        }
        __syncthreads();
#pragma unroll
        for (int mt = 0; mt < MT; mt++)
#pragma unroll
            for (int d = 0; d < 2; d++) {
                int rr = mt * 16 + 8 * d + g;
                float S = 0.f, Q = 0.f;
#pragma unroll
                for (int w = 0; w < NWN; w++) { S += redS[wm][rr][w]; Q += redQ[wm][rr][w]; }
                float mean = S * (1.0f / NCOLS);
                float var  = Q * (1.0f / NCOLS) - mean * mean;
                float rstd = rsqrtf(var + LN_EPS);
                int grow = bm0 + wm * 32 + rr;
                if (grow >= M) continue;
#pragma unroll
                for (int nt = 0; nt < NT; nt++) {
                    int col = wn * 48 + nt * 8 + 2 * t;
                    float nv0 = (acc[mt][nt][2 * d]     - mean) * rstd * gw[col]     + bw[col];
                    float nv1 = (acc[mt][nt][2 * d + 1] - mean) * rstd * gw[col + 1] + bw[col + 1];
                    float o0, o1;
                    if constexpr (EPI == EPI_LN_GELU) {
                        o0 = gelu_exact(nv0);
                        o1 = gelu_exact(nv1);
                        if (res) {
                            float2 rv = *(const float2*)&res[(size_t)grow * NCOLS + col];
                            o0 = (1.f - ALPHA) * rv.x + ALPHA * o0;
                            o1 = (1.f - ALPHA) * rv.y + ALPHA * o1;
                        }
                    } else {
                        o0 = nv0; o1 = nv1;
                    }
                    *(float2*)&out[(size_t)grow * NCOLS + col] = make_float2(o0, o1);
                }
            }
    }
}

// ---------------- final tiny classifier ----------------
__global__ void k_logits(const float* __restrict__ t2, const float* __restrict__ clsW,
                         const float* __restrict__ clsb, float* __restrict__ out, int D) {
    int warp = (blockIdx.x * blockDim.x + threadIdx.x) >> 5;
    int lane = threadIdx.x & 31;
    if (warp >= D) return;
    const float* r = t2 + (size_t)warp * HHALF;
    float a0 = 0.f, a1 = 0.f;
    for (int k = lane; k < HHALF; k += 32) {
        float x = r[k];
        a0 = fmaf(x, clsW[2 * k],     a0);
        a1 = fmaf(x, clsW[2 * k + 1], a1);
    }
    for (int off = 16; off > 0; off >>= 1) {
        a0 += __shfl_down_sync(0xffffffffu, a0, off);
        a1 += __shfl_down_sync(0xffffffffu, a1, off);
    }
    if (lane == 0) {
        out[2 * warp]     = a0 + clsb[0];
        out[2 * warp + 1] = a1 + clsb[1];
    }
}

// ---------------- launch ----------------
extern "C" void kernel_launch(void* const* d_in, const int* in_sizes, int n_in,
                              void* d_out, int out_size) {
    const int*   A_rows  = (const int*)  d_in[0];
    const int*   A_cols  = (const int*)  d_in[1];
    const float* A_vals  = (const float*)d_in[2];
    const int*   X_rows  = (const int*)  d_in[3];
    const int*   X_cols  = (const int*)  d_in[4];
    const float* X_vals  = (const float*)d_in[5];
    const float* emb     = (const float*)d_in[7];
    const float* W1      = (const float*)d_in[8];
    const float* W2      = (const float*)d_in[9];
    const float* W3      = (const float*)d_in[10];
    const float* g1      = (const float*)d_in[11];
    const float* b1      = (const float*)d_in[12];
    const float* g2      = (const float*)d_in[13];
    const float* b2      = (const float*)d_in[14];
    const float* g3      = (const float*)d_in[15];
    const float* b3      = (const float*)d_in[16];
    const float* mlp_W1  = (const float*)d_in[17];
    const float* mlp_b1  = (const float*)d_in[18];
    const float* mlp_g   = (const float*)d_in[19];
    const float* mlp_bn  = (const float*)d_in[20];
    const float* mlp_W2  = (const float*)d_in[21];
    const float* mlp_b2  = (const float*)d_in[22];
    const float* cls_W   = (const float*)d_in[23];
    const float* cls_b   = (const float*)d_in[24];
    const float* gate_W1 = (const float*)d_in[25];
    const float* gate_b1 = (const float*)d_in[26];
    const float* gate_W2 = (const float*)d_in[27];
    const float* gate_b2 = (const float*)d_in[28];

    const int E   = in_sizes[0];
    const int NNZ = in_sizes[3];
    const int N   = in_sizes[7] / HDIM;
    const int D   = out_size / 2;
    float* out = (float*)d_out;

    float *buf1, *buf2, *docH, *docH0, *hidden, *doc, *t2;
    int *Arp, *Awp, *Aci, *Xrp, *Xwp, *Xci;
    float *Av, *Xv;
    uint32_t *Wh;
    cudaGetSymbolAddress((void**)&buf1,   g_buf1);
    cudaGetSymbolAddress((void**)&buf2,   g_buf2);
    cudaGetSymbolAddress((void**)&docH,   g_docH);
    cudaGetSymbolAddress((void**)&docH0,  g_docH0);
    cudaGetSymbolAddress((void**)&hidden, g_hidden);
    cudaGetSymbolAddress((void**)&doc,    g_doc);
    cudaGetSymbolAddress((void**)&t2,     g_t2);
    cudaGetSymbolAddress((void**)&Arp, g_Arp);
    cudaGetSymbolAddress((void**)&Awp, g_Awp);
    cudaGetSymbolAddress((void**)&Aci, g_Aci);
    cudaGetSymbolAddress((void**)&Av,  g_Av);
    cudaGetSymbolAddress((void**)&Xrp, g_Xrp);
    cudaGetSymbolAddress((void**)&Xwp, g_Xwp);
    cudaGetSymbolAddress((void**)&Xci, g_Xci);
    cudaGetSymbolAddress((void**)&Xv,  g_Xv);
    cudaGetSymbolAddress((void**)&Wh,  g_Wh);

    const int gcnGrid = (N + 63) / 64;
    const int docGrid = (D + 63) / 64;

    // ---- pre-pack all weights to fp16 (k-pair-major) ----
    {
        const int n384 = 192 * 384;
        k_wpack<<<(n384 + 255) / 256, 256>>>(W1,      192, 384, Wh + OFF_W1);
        k_wpack<<<(n384 + 255) / 256, 256>>>(W2,      192, 384, Wh + OFF_W2);
        k_wpack<<<(n384 + 255) / 256, 256>>>(W3,      192, 384, Wh + OFF_W3);
        k_wpack<<<(n384 + 255) / 256, 256>>>(gate_W2, 192, 384, Wh + OFF_GW2);
        k_wpack<<<(n384 + 255) / 256, 256>>>(mlp_W1,  192, 384, Wh + OFF_MW1);
        const int ngw1 = 384 * 384;
        k_wpack<<<(ngw1 + 255) / 256, 256>>>(gate_W1, 384, 384, Wh + OFF_GW1);
        k_wpack<<<(192 * 192 + 255) / 256, 256>>>(mlp_W2, 192, 192, Wh + OFF_MW2);
    }

    // ---- build CSR for A and X ----
    k_zero_i32<<<(N + 2 + 255) / 256, 256>>>(Arp, N + 1);
    k_hist    <<<(E + 255) / 256, 256>>>(A_rows, E, Arp);
    k_scan_excl<<<1, 1024>>>(Arp, N, Awp);
    k_scatter <<<(E + 255) / 256, 256>>>(A_rows, A_cols, A_vals, E, Awp, Aci, Av);

    k_zero_i32<<<(D + 2 + 255) / 256, 256>>>(Xrp, D + 1);
    k_hist    <<<(NNZ + 255) / 256, 256>>>(X_rows, NNZ, Xrp);
    k_scan_excl<<<1, 1024>>>(Xrp, D, Xwp);
    k_scatter <<<(NNZ + 255) / 256, 256>>>(X_rows, X_cols, X_vals, NNZ, Xwp, Xci, Xv);

    // ---- 3 residual GCN blocks (2-pass: word chain amplifies errors) ----
    k_spmm<<<N, 96>>>(Arp, Aci, Av, emb, buf1);
    k_gemm<HDIM, EPI_LN_GELU, 2><<<gcnGrid, 512>>>(buf1, nullptr, HDIM, HDIM,
        Wh + OFF_W1, nullptr, g1, b1, nullptr, nullptr, nullptr, buf2, N);

    k_spmm<<<N, 96>>>(Arp, Aci, Av, buf2, buf1);
    k_gemm<HDIM, EPI_LN_GELU, 2><<<gcnGrid, 512>>>(buf1, nullptr, HDIM, HDIM,
        Wh + OFF_W2, nullptr, g2, b2, nullptr, nullptr, nullptr, buf2, N);

    k_spmm<<<N, 96>>>(Arp, Aci, Av, buf2, buf1);
    k_gemm<HDIM, EPI_LN_GELU, 2><<<gcnGrid, 512>>>(buf1, nullptr, HDIM, HDIM,
        Wh + OFF_W3, nullptr, g3, b3, nullptr, nullptr, emb, buf2, N);

    // ---- doc aggregation (fused: docH from word_H, docH0 from emb) ----
    k_spmm2<<<D, 96>>>(Xrp, Xci, Xv, buf2, emb, docH, docH0);

    // ---- doc head (1-pass: late stage, low amplification) ----
    // gate hidden = gelu([docH | docH0] @ gate_W1 + gate_b1)
    k_gemm<HDIM, EPI_GELU, 1><<<docGrid, 512>>>(docH, docH0, 2 * HDIM, HDIM,
        Wh + OFF_GW1, gate_b1, nullptr, nullptr, nullptr, nullptr, nullptr, hidden, D);

    // gate = sigmoid(hidden @ gate_W2 + gate_b2); doc = gate*docH + (1-gate)*docH0
    k_gemm<HDIM, EPI_GATE, 1><<<docGrid, 512>>>(hidden, nullptr, HDIM, HDIM,
        Wh + OFF_GW2, gate_b2, nullptr, nullptr, docH, docH0, nullptr, doc, D);

    // mlp1: ln(gelu(doc @ mlp_W1 + mlp_b1))
    k_gemm<HDIM, EPI_GELU_LN, 1><<<docGrid, 512>>>(doc, nullptr, HDIM, HDIM,
        Wh + OFF_MW1, mlp_b1, mlp_g, mlp_bn, nullptr, nullptr, nullptr, hidden, D);

    // mlp2: gelu(hidden @ mlp_W2 + mlp_b2) -> [D, 192]
    k_gemm<HHALF, EPI_GELU, 1><<<docGrid, 256>>>(hidden, nullptr, HDIM, HDIM,
        Wh + OFF_MW2, mlp_b2, nullptr, nullptr, nullptr, nullptr, nullptr, t2, D);

    // logits
    k_logits<<<(D + 7) / 8, 256>>>(t2, cls_W, cls_b, out, D);
}

// round 15
// speedup vs baseline: 1.2907x; 1.0452x over previous
#include <cuda_runtime.h>
#include <cuda_fp16.h>
#include <math.h>
#include <stdint.h>

// ---------------- problem constants ----------------
#define HDIM  384
#define HHALF 192
constexpr int   MAXN   = 40000;
constexpr int   MAXD   = 20000;
constexpr int   MAXE   = 800000;
constexpr int   MAXNNZ = 800000;
constexpr float ALPHA  = 0.65f;
constexpr float LN_EPS = 1e-5f;

// weight fp16 pool offsets (u32 units, layout [K/2][NCOLS] f16x2 k-pairs)
constexpr int OFF_W1  = 0;
constexpr int OFF_W2  = 73728;
constexpr int OFF_W3  = 147456;
constexpr int OFF_GW2 = 221184;
constexpr int OFF_MW1 = 294912;
constexpr int OFF_GW1 = 368640;   // K=768 x 384
constexpr int OFF_MW2 = 516096;   // 192 x 192
constexpr int WPOOL   = 552960;

// ---------------- static scratch ----------------
__device__ float g_buf1[(size_t)MAXN * HDIM];
__device__ float g_buf2[(size_t)MAXN * HDIM];
__device__ float g_docH [(size_t)MAXD * HDIM];
__device__ float g_docH0[(size_t)MAXD * HDIM];
__device__ float g_hidden[(size_t)MAXD * HDIM];
__device__ float g_doc  [(size_t)MAXD * HDIM];
__device__ float g_t2   [(size_t)MAXD * HHALF];

__device__ __align__(16) uint32_t g_Wh[WPOOL];
// combined fp16 doc-gather image: per word row, 768 halves = [word_H(384) | emb(384)]
__device__ __align__(16) uint32_t g_wh16[(size_t)MAXN * 384];

__device__ int   g_Arp[MAXN + 1];
__device__ int   g_Awp[MAXN + 1];
__device__ int   g_Aci[MAXE];
__device__ float g_Av [MAXE];
__device__ int   g_Xrp[MAXD + 1];
__device__ int   g_Xwp[MAXD + 1];
__device__ int   g_Xci[MAXNNZ];
__device__ float g_Xv [MAXNNZ];

// ---------------- helpers ----------------
__device__ __forceinline__ float gelu_exact(float x) {
    return 0.5f * x * (1.0f + erff(x * 0.70710678118654752f));
}
__device__ __forceinline__ float sigmoidf_(float x) {
    return 1.0f / (1.0f + __expf(-x));
}
__device__ __forceinline__ uint32_t cvth2(float x, float y) {
    __half2 h = __floats2half2_rn(x, y);
    return *reinterpret_cast<uint32_t*>(&h);
}
// split (x,y): hi = f16x2(x,y), lo = f16x2 of residuals
__device__ __forceinline__ void hsplit2(float x, float y, uint32_t& h, uint32_t& l) {
    __half2 hh = __floats2half2_rn(x, y);
    float2 f = __half22float2(hh);
    __half2 ll = __floats2half2_rn(x - f.x, y - f.y);
    h = *reinterpret_cast<uint32_t*>(&hh);
    l = *reinterpret_cast<uint32_t*>(&ll);
}
__device__ __forceinline__ float2 h2f2(uint32_t p) {
    __half2 h = *reinterpret_cast<__half2*>(&p);
    return __half22float2(h);
}
__device__ __forceinline__ void mma_f16(float* d, const uint32_t* a, const uint32_t* b) {
    asm volatile(
        "mma.sync.aligned.m16n8k16.row.col.f32.f16.f16.f32 "
        "{%0,%1,%2,%3}, {%4,%5,%6,%7}, {%8,%9}, {%0,%1,%2,%3};"
        : "+f"(d[0]), "+f"(d[1]), "+f"(d[2]), "+f"(d[3])
        : "r"(a[0]), "r"(a[1]), "r"(a[2]), "r"(a[3]), "r"(b[0]), "r"(b[1]));
}
__device__ __forceinline__ void fma4(float4& a, float v, const float4& m) {
    a.x = fmaf(v, m.x, a.x);
    a.y = fmaf(v, m.y, a.y);
    a.z = fmaf(v, m.z, a.z);
    a.w = fmaf(v, m.w, a.w);
}

// ---------------- weight fp16 pack ----------------
__global__ void k_wpack(const float* __restrict__ W, int KP, int NC,
                        uint32_t* __restrict__ hi) {
    int idx = blockIdx.x * blockDim.x + threadIdx.x;
    if (idx >= KP * NC) return;
    int kp = idx / NC, n = idx - kp * NC;
    float x = W[(size_t)(2 * kp) * NC + n];
    float y = W[(size_t)(2 * kp + 1) * NC + n];
    hi[idx] = cvth2(x, y);
}

// emb -> fp16 into second half of combined image: wh16[row*384 + 192 + j]
__global__ void k_embh(const float* __restrict__ emb, uint32_t* __restrict__ wh16, int n) {
    int idx = blockIdx.x * blockDim.x + threadIdx.x;
    if (idx >= n * 192) return;
    int row = idx / 192, j = idx - row * 192;
    float2 v = *(const float2*)(emb + (size_t)row * HDIM + 2 * j);
    wh16[(size_t)row * 384 + 192 + j] = cvth2(v.x, v.y);
}

// ---------------- CSR build ----------------
__global__ void k_zero_i32(int* p, int n) {
    int i = blockIdx.x * blockDim.x + threadIdx.x;
    if (i < n) p[i] = 0;
}

__global__ void k_hist(const int* __restrict__ rows, int ne, int* __restrict__ cnt) {
    int e = blockIdx.x * blockDim.x + threadIdx.x;
    if (e < ne) atomicAdd(&cnt[rows[e]], 1);
}

__global__ void k_scan_excl(int* __restrict__ data, int n, int* __restrict__ wp) {
    __shared__ int sums[1024];
    int t = threadIdx.x;
    int C = (n + 1023) / 1024;
    int start = t * C;
    int end   = min(start + C, n);

    int s = 0;
    for (int i = start; i < end; i++) s += data[i];
    sums[t] = s;
    __syncthreads();

    for (int off = 1; off < 1024; off <<= 1) {
        int add = (t >= off) ? sums[t - off] : 0;
        __syncthreads();
        sums[t] += add;
        __syncthreads();
    }

    int run = sums[t] - s;
    for (int i = start; i < end; i++) {
        int c = data[i];
        data[i] = run;
        wp[i]   = run;
        run += c;
    }
    if (t == 1023) data[n] = sums[1023];
}

__global__ void k_scatter(const int* __restrict__ rows, const int* __restrict__ cols,
                          const float* __restrict__ vals, int ne,
                          int* __restrict__ wp, int* __restrict__ ci,
                          float* __restrict__ cv) {
    int e = blockIdx.x * blockDim.x + threadIdx.x;
    if (e < ne) {
        int pos = atomicAdd(&wp[rows[e]], 1);
        ci[pos] = cols[e];
        cv[pos] = vals[e];
    }
}

// ---------------- SpMM (CSR gather, float4, unroll-4, fp32) ----------------
__global__ void __launch_bounds__(96)
k_spmm(const int* __restrict__ rp, const int* __restrict__ ci,
       const float* __restrict__ cv, const float* __restrict__ M,
       float* __restrict__ out) {
    const int r = blockIdx.x;
    const int t = threadIdx.x;
    const int s = rp[r], e = rp[r + 1];
    const float4* __restrict__ M4 = (const float4*)M;
    float4 acc = make_float4(0.f, 0.f, 0.f, 0.f);

    int j = s;
    for (; j + 4 <= e; j += 4) {
        int   c0 = ci[j],     c1 = ci[j + 1], c2 = ci[j + 2], c3 = ci[j + 3];
        float v0 = cv[j],     v1 = cv[j + 1], v2 = cv[j + 2], v3 = cv[j + 3];
        float4 m0 = M4[(size_t)c0 * 96 + t];
        float4 m1 = M4[(size_t)c1 * 96 + t];
        float4 m2 = M4[(size_t)c2 * 96 + t];
        float4 m3 = M4[(size_t)c3 * 96 + t];
        fma4(acc, v0, m0);
        fma4(acc, v1, m1);
        fma4(acc, v2, m2);
        fma4(acc, v3, m3);
    }
    for (; j < e; j++) {
        float4 m = M4[(size_t)ci[j] * 96 + t];
        fma4(acc, cv[j], m);
    }
    ((float4*)(out + (size_t)r * HDIM))[t] = acc;
}

// fused doc double-SpMM over combined fp16 image (one uint4 = 8 halves per thread/nnz).
// thread t<48: word_H cols [8t,8t+8) -> docH ; t>=48: emb cols -> docH0.
__global__ void __launch_bounds__(96)
k_spmm2h(const int* __restrict__ rp, const int* __restrict__ ci,
         const float* __restrict__ cv, const uint32_t* __restrict__ MH,
         float* __restrict__ outA, float* __restrict__ outB) {
    const int r = blockIdx.x;
    const int t = threadIdx.x;
    const int s = rp[r], e = rp[r + 1];
    const uint4* __restrict__ M4 = (const uint4*)MH;   // 96 uint4 per row

    float acc[8];
#pragma unroll
    for (int i = 0; i < 8; i++) acc[i] = 0.f;

    auto accum = [&](float v, uint4 m) {
        float2 f0 = h2f2(m.x), f1 = h2f2(m.y), f2 = h2f2(m.z), f3 = h2f2(m.w);
        acc[0] = fmaf(v, f0.x, acc[0]);
        acc[1] = fmaf(v, f0.y, acc[1]);
        acc[2] = fmaf(v, f1.x, acc[2]);
        acc[3] = fmaf(v, f1.y, acc[3]);
        acc[4] = fmaf(v, f2.x, acc[4]);
        acc[5] = fmaf(v, f2.y, acc[5]);
        acc[6] = fmaf(v, f3.x, acc[6]);
        acc[7] = fmaf(v, f3.y, acc[7]);
    };

    int j = s;
    for (; j + 4 <= e; j += 4) {
        int   c0 = ci[j],  c1 = ci[j + 1], c2 = ci[j + 2], c3 = ci[j + 3];
        float v0 = cv[j],  v1 = cv[j + 1], v2 = cv[j + 2], v3 = cv[j + 3];
        uint4 m0 = M4[(size_t)c0 * 96 + t];
        uint4 m1 = M4[(size_t)c1 * 96 + t];
        uint4 m2 = M4[(size_t)c2 * 96 + t];
        uint4 m3 = M4[(size_t)c3 * 96 + t];
        accum(v0, m0);
        accum(v1, m1);
        accum(v2, m2);
        accum(v3, m3);
    }
    for (; j < e; j++) {
        uint4 m = M4[(size_t)ci[j] * 96 + t];
        accum(cv[j], m);
    }

    float* o = (t < 48) ? (outA + (size_t)r * HDIM + 8 * t)
                        : (outB + (size_t)r * HDIM + 8 * (t - 48));
    *(float4*)(o)     = make_float4(acc[0], acc[1], acc[2], acc[3]);
    *(float4*)(o + 4) = make_float4(acc[4], acc[5], acc[6], acc[7]);
}

// ---------------- fp16 split tensor-core GEMM with fused epilogues ----------------
// PASSES=2: A split a=ah+al (exact); PASSES=1: A rounded to fp16.
// out16 (LN_GELU only, non-null): store f16x2 into combined image
// (row stride 384 u32), skipping the fp32 store.
enum { EPI_LN_GELU = 0, EPI_GELU = 1, EPI_GATE = 2, EPI_GELU_LN = 3 };

template <int NCOLS, int EPI, int PASSES>
__global__ void __launch_bounds__(64 * (NCOLS / 48))
k_gemm(const float* __restrict__ A1, const float* __restrict__ A2,
       int K, int K1,
       const uint32_t* __restrict__ Wh,
       const float* __restrict__ bias,
       const float* __restrict__ gw, const float* __restrict__ bw,
       const float* __restrict__ aux1, const float* __restrict__ aux2,
       const float* __restrict__ res,
       float* __restrict__ out, uint32_t* __restrict__ out16, int M) {
    constexpr int NWN     = NCOLS / 48;
    constexpr int THREADS = 64 * NWN;
    constexpr int BM = 64, BK = 16;
    constexpr int MT = 2, NT = 6;
    constexpr int AV4 = BM * BK / 4;
    constexpr int BU4 = (8 * NCOLS) / 4;
    constexpr int BITER = (BU4 + THREADS - 1) / THREADS;
    constexpr int BROW = NCOLS + 8;

    __shared__ uint32_t AsH[BM][12];
    __shared__ uint32_t AsL[PASSES == 2 ? BM : 1][12];
    __shared__ uint32_t BsH[8][BROW];
    __shared__ float redS[2][32][NWN];
    __shared__ float redQ[2][32][NWN];

    const int tid  = threadIdx.x;
    const int lane = tid & 31;
    const int warp = tid >> 5;
    const int wm = warp & 1;
    const int wn = warp >> 1;
    const int g  = lane >> 2;
    const int t  = lane & 3;
    const int bm0 = blockIdx.x * BM;
    const int NC  = K / BK;

    float acc[MT][NT][4];
#pragma unroll
    for (int mt = 0; mt < MT; mt++)
#pragma unroll
        for (int nt = 0; nt < NT; nt++)
#pragma unroll
            for (int c = 0; c < 4; c++) acc[mt][nt][c] = 0.f;

    float4 pa;
    uint4  pbh[BITER];

    auto gload = [&](int k0) {
        const float* Ab;
        int kc, AW;
        if (k0 < K1) { Ab = A1; kc = k0; AW = K1; }
        else         { Ab = A2; kc = k0 - K1; AW = K - K1; }
        if (tid < AV4) {
            int row = tid >> 2, f4 = tid & 3;
            int grow = bm0 + row;
            if (grow < M)
                pa = *(const float4*)(Ab + (size_t)grow * AW + kc + 4 * f4);
            else
                pa = make_float4(0.f, 0.f, 0.f, 0.f);
        }
        const uint4* bh = (const uint4*)(Wh + (size_t)(k0 / 2) * NCOLS);
#pragma unroll
        for (int i = 0; i < BITER; i++) {
            int idx = tid + i * THREADS;
            if (idx < BU4) pbh[i] = bh[idx];
        }
    };
    auto sstore = [&]() {
        if (tid < AV4) {
            int row = tid >> 2, f4 = tid & 3;
            if constexpr (PASSES == 2) {
                uint32_t h0, l0, h1, l1;
                hsplit2(pa.x, pa.y, h0, l0);
                hsplit2(pa.z, pa.w, h1, l1);
                AsH[row][2 * f4]     = h0;
                AsH[row][2 * f4 + 1] = h1;
                AsL[row][2 * f4]     = l0;
                AsL[row][2 * f4 + 1] = l1;
            } else {
                AsH[row][2 * f4]     = cvth2(pa.x, pa.y);
                AsH[row][2 * f4 + 1] = cvth2(pa.z, pa.w);
            }
        }
#pragma unroll
        for (int i = 0; i < BITER; i++) {
            int idx = tid + i * THREADS;
            if (idx < BU4) {
                int off = 4 * idx;
                int r = off / NCOLS, n = off - r * NCOLS;
                *(uint4*)&BsH[r][n] = pbh[i];
            }
        }
    };

    gload(0);
    sstore();
    __syncthreads();

    for (int c = 0; c < NC; c++) {
        if (c + 1 < NC) gload((c + 1) * BK);

        uint32_t ah[MT][4], bh[NT][2];
#pragma unroll
        for (int mt = 0; mt < MT; mt++) {
            int r0 = wm * 32 + mt * 16;
            ah[mt][0] = AsH[r0 + g][t];
            ah[mt][1] = AsH[r0 + g + 8][t];
            ah[mt][2] = AsH[r0 + g][t + 4];
            ah[mt][3] = AsH[r0 + g + 8][t + 4];
        }
#pragma unroll
        for (int nt = 0; nt < NT; nt++) {
            int n0 = wn * 48 + nt * 8 + g;
            bh[nt][0] = BsH[t][n0];
            bh[nt][1] = BsH[t + 4][n0];
        }

#pragma unroll
        for (int nt = 0; nt < NT; nt++)
#pragma unroll
            for (int mt = 0; mt < MT; mt++)
                mma_f16(acc[mt][nt], ah[mt], bh[nt]);

        if constexpr (PASSES == 2) {
            uint32_t al[MT][4];
#pragma unroll
            for (int mt = 0; mt < MT; mt++) {
                int r0 = wm * 32 + mt * 16;
                al[mt][0] = AsL[r0 + g][t];
                al[mt][1] = AsL[r0 + g + 8][t];
                al[mt][2] = AsL[r0 + g][t + 4];
                al[mt][3] = AsL[r0 + g + 8][t + 4];
            }
#pragma unroll
            for (int nt = 0; nt < NT; nt++)
#pragma unroll
                for (int mt = 0; mt < MT; mt++)
                    mma_f16(acc[mt][nt], al[mt], bh[nt]);
        }

        __syncthreads();
        if (c + 1 < NC) {
            sstore();
            __syncthreads();
        }
    }

    // -------- epilogues --------
    // acc[mt][nt][c]: row = wm*32 + mt*16 + 8*(c>>1) + g ; col = wn*48 + nt*8 + 2*t + (c&1)
    if constexpr (EPI == EPI_GELU) {
#pragma unroll
        for (int mt = 0; mt < MT; mt++)
#pragma unroll
            for (int d = 0; d < 2; d++) {
                int grow = bm0 + wm * 32 + mt * 16 + 8 * d + g;
                if (grow >= M) continue;
#pragma unroll
                for (int nt = 0; nt < NT; nt++) {
                    int col = wn * 48 + nt * 8 + 2 * t;
                    float v0 = acc[mt][nt][2 * d]     + (bias ? bias[col]     : 0.f);
                    float v1 = acc[mt][nt][2 * d + 1] + (bias ? bias[col + 1] : 0.f);
                    *(float2*)&out[(size_t)grow * NCOLS + col] =
                        make_float2(gelu_exact(v0), gelu_exact(v1));
                }
            }
    } else if constexpr (EPI == EPI_GATE) {
#pragma unroll
        for (int mt = 0; mt < MT; mt++)
#pragma unroll
            for (int d = 0; d < 2; d++) {
                int grow = bm0 + wm * 32 + mt * 16 + 8 * d + g;
                if (grow >= M) continue;
#pragma unroll
                for (int nt = 0; nt < NT; nt++) {
                    int col = wn * 48 + nt * 8 + 2 * t;
                    size_t idx = (size_t)grow * NCOLS + col;
                    float s0 = sigmoidf_(acc[mt][nt][2 * d]     + bias[col]);
                    float s1 = sigmoidf_(acc[mt][nt][2 * d + 1] + bias[col + 1]);
                    float2 h1 = *(const float2*)&aux1[idx];
                    float2 h0 = *(const float2*)&aux2[idx];
                    *(float2*)&out[idx] = make_float2(
                        s0 * h1.x + (1.f - s0) * h0.x,
                        s1 * h1.y + (1.f - s1) * h0.y);
                }
            }
    } else {
        float sm_[MT][2], sq_[MT][2];
#pragma unroll
        for (int mt = 0; mt < MT; mt++)
#pragma unroll
            for (int d = 0; d < 2; d++) { sm_[mt][d] = 0.f; sq_[mt][d] = 0.f; }

#pragma unroll
        for (int mt = 0; mt < MT; mt++)
#pragma unroll
            for (int nt = 0; nt < NT; nt++) {
                int col = wn * 48 + nt * 8 + 2 * t;
#pragma unroll
                for (int d = 0; d < 2; d++) {
                    float v0 = acc[mt][nt][2 * d];
                    float v1 = acc[mt][nt][2 * d + 1];
                    if constexpr (EPI == EPI_GELU_LN) {
                        v0 = gelu_exact(v0 + bias[col]);
                        v1 = gelu_exact(v1 + bias[col + 1]);
                        acc[mt][nt][2 * d] = v0;
                        acc[mt][nt][2 * d + 1] = v1;
                    }
                    sm_[mt][d] += v0 + v1;
                    sq_[mt][d] += v0 * v0 + v1 * v1;
                }
            }
#pragma unroll
        for (int mt = 0; mt < MT; mt++)
#pragma unroll
            for (int d = 0; d < 2; d++) {
                float s = sm_[mt][d], q = sq_[mt][d];
                s += __shfl_xor_sync(0xffffffffu, s, 1);
                q += __shfl_xor_sync(0xffffffffu, q, 1);
                s += __shfl_xor_sync(0xffffffffu, s, 2);
                q += __shfl_xor_sync(0xffffffffu, q, 2);
                sm_[mt][d] = s; sq_[mt][d] = q;
            }
        if (t == 0) {
#pragma unroll
            for (int mt = 0; mt < MT; mt++)
#pragma unroll
                for (int d = 0; d < 2; d++) {
                    int rr = mt * 16 + 8 * d + g;
                    redS[wm][rr][wn] = sm_[mt][d];
                    redQ[wm][rr][wn] = sq_[mt][d];
                }
        }
        __syncthreads();
#pragma unroll
        for (int mt = 0; mt < MT; mt++)
#pragma unroll
            for (int d = 0; d < 2; d++) {
                int rr = mt * 16 + 8 * d + g;
                float S = 0.f, Q = 0.f;
#pragma unroll
                for (int w = 0; w < NWN; w++) { S += redS[wm][rr][w]; Q += redQ[wm][rr][w]; }
                float mean = S * (1.0f / NCOLS);
                float var  = Q * (1.0f / NCOLS) - mean * mean;
                float rstd = rsqrtf(var + LN_EPS);
                int grow = bm0 + wm * 32 + rr;
                if (grow >= M) continue;
#pragma unroll
                for (int nt = 0; nt < NT; nt++) {
                    int col = wn * 48 + nt * 8 + 2 * t;
                    float nv0 = (acc[mt][nt][2 * d]     - mean) * rstd * gw[col]     + bw[col];
                    float nv1 = (acc[mt][nt][2 * d + 1] - mean) * rstd * gw[col + 1] + bw[col + 1];
                    float o0, o1;
                    if constexpr (EPI == EPI_LN_GELU) {
                        o0 = gelu_exact(nv0);
                        o1 = gelu_exact(nv1);
                        if (res) {
                            float2 rv = *(const float2*)&res[(size_t)grow * NCOLS + col];
                            o0 = (1.f - ALPHA) * rv.x + ALPHA * o0;
                            o1 = (1.f - ALPHA) * rv.y + ALPHA * o1;
                        }
                    } else {
                        o0 = nv0; o1 = nv1;
                    }
                    if (EPI == EPI_LN_GELU && out16) {
                        // word_H half of combined image: row stride 384 u32
                        out16[(size_t)grow * 384 + (col >> 1)] = cvth2(o0, o1);
                    } else {
                        *(float2*)&out[(size_t)grow * NCOLS + col] = make_float2(o0, o1);
                    }
                }
            }
    }
}

// ---------------- final tiny classifier ----------------
__global__ void k_logits(const float* __restrict__ t2, const float* __restrict__ clsW,
                         const float* __restrict__ clsb, float* __restrict__ out, int D) {
    int warp = (blockIdx.x * blockDim.x + threadIdx.x) >> 5;
    int lane = threadIdx.x & 31;
    if (warp >= D) return;
    const float* r = t2 + (size_t)warp * HHALF;
    float a0 = 0.f, a1 = 0.f;
    for (int k = lane; k < HHALF; k += 32) {
        float x = r[k];
        a0 = fmaf(x, clsW[2 * k],     a0);
        a1 = fmaf(x, clsW[2 * k + 1], a1);
    }
    for (int off = 16; off > 0; off >>= 1) {
        a0 += __shfl_down_sync(0xffffffffu, a0, off);
        a1 += __shfl_down_sync(0xffffffffu, a1, off);
    }
    if (lane == 0) {
        out[2 * warp]     = a0 + clsb[0];
        out[2 * warp + 1] = a1 + clsb[1];
    }
}

// ---------------- launch ----------------
extern "C" void kernel_launch(void* const* d_in, const int* in_sizes, int n_in,
                              void* d_out, int out_size) {
    const int*   A_rows  = (const int*)  d_in[0];
    const int*   A_cols  = (const int*)  d_in[1];
    const float* A_vals  = (const float*)d_in[2];
    const int*   X_rows  = (const int*)  d_in[3];
    const int*   X_cols  = (const int*)  d_in[4];
    const float* X_vals  = (const float*)d_in[5];
    const float* emb     = (const float*)d_in[7];
    const float* W1      = (const float*)d_in[8];
    const float* W2      = (const float*)d_in[9];
    const float* W3      = (const float*)d_in[10];
    const float* g1      = (const float*)d_in[11];
    const float* b1      = (const float*)d_in[12];
    const float* g2      = (const float*)d_in[13];
    const float* b2      = (const float*)d_in[14];
    const float* g3      = (const float*)d_in[15];
    const float* b3      = (const float*)d_in[16];
    const float* mlp_W1  = (const float*)d_in[17];
    const float* mlp_b1  = (const float*)d_in[18];
    const float* mlp_g   = (const float*)d_in[19];
    const float* mlp_bn  = (const float*)d_in[20];
    const float* mlp_W2  = (const float*)d_in[21];
    const float* mlp_b2  = (const float*)d_in[22];
    const float* cls_W   = (const float*)d_in[23];
    const float* cls_b   = (const float*)d_in[24];
    const float* gate_W1 = (const float*)d_in[25];
    const float* gate_b1 = (const float*)d_in[26];
    const float* gate_W2 = (const float*)d_in[27];
    const float* gate_b2 = (const float*)d_in[28];

    const int E   = in_sizes[0];
    const int NNZ = in_sizes[3];
    const int N   = in_sizes[7] / HDIM;
    const int D   = out_size / 2;
    float* out = (float*)d_out;

    float *buf1, *buf2, *docH, *docH0, *hidden, *doc, *t2;
    int *Arp, *Awp, *Aci, *Xrp, *Xwp, *Xci;
    float *Av, *Xv;
    uint32_t *Wh, *wh16;
    cudaGetSymbolAddress((void**)&buf1,   g_buf1);
    cudaGetSymbolAddress((void**)&buf2,   g_buf2);
    cudaGetSymbolAddress((void**)&docH,   g_docH);
    cudaGetSymbolAddress((void**)&docH0,  g_docH0);
    cudaGetSymbolAddress((void**)&hidden, g_hidden);
    cudaGetSymbolAddress((void**)&doc,    g_doc);
    cudaGetSymbolAddress((void**)&t2,     g_t2);
    cudaGetSymbolAddress((void**)&Arp, g_Arp);
    cudaGetSymbolAddress((void**)&Awp, g_Awp);
    cudaGetSymbolAddress((void**)&Aci, g_Aci);
    cudaGetSymbolAddress((void**)&Av,  g_Av);
    cudaGetSymbolAddress((void**)&Xrp, g_Xrp);
    cudaGetSymbolAddress((void**)&Xwp, g_Xwp);
    cudaGetSymbolAddress((void**)&Xci, g_Xci);
    cudaGetSymbolAddress((void**)&Xv,  g_Xv);
    cudaGetSymbolAddress((void**)&Wh,  g_Wh);
    cudaGetSymbolAddress((void**)&wh16, g_wh16);

    const int gcnGrid = (N + 63) / 64;
    const int docGrid = (D + 63) / 64;

    // ---- pre-pack weights to fp16 + emb fp16 half of combined image ----
    {
        const int n384 = 192 * 384;
        k_wpack<<<(n384 + 255) / 256, 256>>>(W1,      192, 384, Wh + OFF_W1);
        k_wpack<<<(n384 + 255) / 256, 256>>>(W2,      192, 384, Wh + OFF_W2);
        k_wpack<<<(n384 + 255) / 256, 256>>>(W3,      192, 384, Wh + OFF_W3);
        k_wpack<<<(n384 + 255) / 256, 256>>>(gate_W2, 192, 384, Wh + OFF_GW2);
        k_wpack<<<(n384 + 255) / 256, 256>>>(mlp_W1,  192, 384, Wh + OFF_MW1);
        const int ngw1 = 384 * 384;
        k_wpack<<<(ngw1 + 255) / 256, 256>>>(gate_W1, 384, 384, Wh + OFF_GW1);
        k_wpack<<<(192 * 192 + 255) / 256, 256>>>(mlp_W2, 192, 192, Wh + OFF_MW2);
        k_embh <<<(N * 192 + 255) / 256, 256>>>(emb, wh16, N);
    }

    // ---- build CSR for A and X ----
    k_zero_i32<<<(N + 2 + 255) / 256, 256>>>(Arp, N + 1);
    k_hist    <<<(E + 255) / 256, 256>>>(A_rows, E, Arp);
    k_scan_excl<<<1, 1024>>>(Arp, N, Awp);
    k_scatter <<<(E + 255) / 256, 256>>>(A_rows, A_cols, A_vals, E, Awp, Aci, Av);

    k_zero_i32<<<(D + 2 + 255) / 256, 256>>>(Xrp, D + 1);
    k_hist    <<<(NNZ + 255) / 256, 256>>>(X_rows, NNZ, Xrp);
    k_scan_excl<<<1, 1024>>>(Xrp, D, Xwp);
    k_scatter <<<(NNZ + 255) / 256, 256>>>(X_rows, X_cols, X_vals, NNZ, Xwp, Xci, Xv);

    // ---- 3 residual GCN blocks (2-pass GEMMs) ----
    k_spmm<<<N, 96>>>(Arp, Aci, Av, emb, buf1);
    k_gemm<HDIM, EPI_LN_GELU, 2><<<gcnGrid, 512>>>(buf1, nullptr, HDIM, HDIM,
        Wh + OFF_W1, nullptr, g1, b1, nullptr, nullptr, nullptr, buf2, nullptr, N);

    k_spmm<<<N, 96>>>(Arp, Aci, Av, buf2, buf1);
    k_gemm<HDIM, EPI_LN_GELU, 2><<<gcnGrid, 512>>>(buf1, nullptr, HDIM, HDIM,
        Wh + OFF_W2, nullptr, g2, b2, nullptr, nullptr, nullptr, buf2, nullptr, N);

    k_spmm<<<N, 96>>>(Arp, Aci, Av, buf2, buf1);
    // block 3 writes word_H directly as fp16 into combined image (no fp32 store)
    k_gemm<HDIM, EPI_LN_GELU, 2><<<gcnGrid, 512>>>(buf1, nullptr, HDIM, HDIM,
        Wh + OFF_W3, nullptr, g3, b3, nullptr, nullptr, emb, buf2, wh16, N);

    // ---- doc aggregation over combined fp16 image ----
    k_spmm2h<<<D, 96>>>(Xrp, Xci, Xv, wh16, docH, docH0);

    // ---- doc head (1-pass GEMMs) ----
    k_gemm<HDIM, EPI_GELU, 1><<<docGrid, 512>>>(docH, docH0, 2 * HDIM, HDIM,
        Wh + OFF_GW1, gate_b1, nullptr, nullptr, nullptr, nullptr, nullptr, hidden, nullptr, D);

    k_gemm<HDIM, EPI_GATE, 1><<<docGrid, 512>>>(hidden, nullptr, HDIM, HDIM,
        Wh + OFF_GW2, gate_b2, nullptr, nullptr, docH, docH0, nullptr, doc, nullptr, D);

    k_gemm<HDIM, EPI_GELU_LN, 1><<<docGrid, 512>>>(doc, nullptr, HDIM, HDIM,
        Wh + OFF_MW1, mlp_b1, mlp_g, mlp_bn, nullptr, nullptr, nullptr, hidden, nullptr, D);

    k_gemm<HHALF, EPI_GELU, 1><<<docGrid, 256>>>(hidden, nullptr, HDIM, HDIM,
        Wh + OFF_MW2, mlp_b2, nullptr, nullptr, nullptr, nullptr, nullptr, t2, nullptr, D);

    // logits
    k_logits<<<(D + 7) / 8, 256>>>(t2, cls_W, cls_b, out, D);
}

// round 16
// speedup vs baseline: 1.3393x; 1.0377x over previous
#include <cuda_runtime.h>
#include <cuda_fp16.h>
#include <math.h>
#include <stdint.h>

// ---------------- problem constants ----------------
#define HDIM  384
#define HHALF 192
constexpr int   MAXN   = 40000;
constexpr int   MAXD   = 20000;
constexpr int   MAXE   = 800000;
constexpr int   MAXNNZ = 800000;
constexpr float ALPHA  = 0.65f;
constexpr float LN_EPS = 1e-5f;

// weight fp16 pool offsets (u32 units, layout [K/2][NCOLS] f16x2 k-pairs)
constexpr int OFF_W1  = 0;
constexpr int OFF_W2  = 73728;
constexpr int OFF_W3  = 147456;
constexpr int OFF_GW2 = 221184;
constexpr int OFF_MW1 = 294912;
constexpr int OFF_GW1 = 368640;   // K=768 x 384
constexpr int OFF_MW2 = 516096;   // 192 x 192
constexpr int WPOOL   = 552960;

// ---------------- static scratch ----------------
__device__ float g_buf1[(size_t)MAXN * HDIM];
__device__ float g_docH [(size_t)MAXD * HDIM];
__device__ float g_docH0[(size_t)MAXD * HDIM];
__device__ float g_hidden[(size_t)MAXD * HDIM];
__device__ float g_doc  [(size_t)MAXD * HDIM];
__device__ float g_t2   [(size_t)MAXD * HHALF];

__device__ __align__(16) uint32_t g_Wh[WPOOL];
// fp16 intermediate word image (blocks 1/2 output): [N][192] u32 = 384 halves/row
__device__ __align__(16) uint32_t g_h16[(size_t)MAXN * 192];
// combined fp16 doc-gather image: per word row, 768 halves = [word_H(384) | emb(384)]
__device__ __align__(16) uint32_t g_wh16[(size_t)MAXN * 384];

__device__ int   g_Arp[MAXN + 1];
__device__ int   g_Awp[MAXN + 1];
__device__ int   g_Aci[MAXE];
__device__ float g_Av [MAXE];
__device__ int   g_Xrp[MAXD + 1];
__device__ int   g_Xwp[MAXD + 1];
__device__ int   g_Xci[MAXNNZ];
__device__ float g_Xv [MAXNNZ];

// ---------------- helpers ----------------
__device__ __forceinline__ float gelu_exact(float x) {
    return 0.5f * x * (1.0f + erff(x * 0.70710678118654752f));
}
__device__ __forceinline__ float sigmoidf_(float x) {
    return 1.0f / (1.0f + __expf(-x));
}
__device__ __forceinline__ uint32_t cvth2(float x, float y) {
    __half2 h = __floats2half2_rn(x, y);
    return *reinterpret_cast<uint32_t*>(&h);
}
// split (x,y): hi = f16x2(x,y), lo = f16x2 of residuals
__device__ __forceinline__ void hsplit2(float x, float y, uint32_t& h, uint32_t& l) {
    __half2 hh = __floats2half2_rn(x, y);
    float2 f = __half22float2(hh);
    __half2 ll = __floats2half2_rn(x - f.x, y - f.y);
    h = *reinterpret_cast<uint32_t*>(&hh);
    l = *reinterpret_cast<uint32_t*>(&ll);
}
__device__ __forceinline__ float2 h2f2(uint32_t p) {
    __half2 h = *reinterpret_cast<__half2*>(&p);
    return __half22float2(h);
}
__device__ __forceinline__ void mma_f16(float* d, const uint32_t* a, const uint32_t* b) {
    asm volatile(
        "mma.sync.aligned.m16n8k16.row.col.f32.f16.f16.f32 "
        "{%0,%1,%2,%3}, {%4,%5,%6,%7}, {%8,%9}, {%0,%1,%2,%3};"
        : "+f"(d[0]), "+f"(d[1]), "+f"(d[2]), "+f"(d[3])
        : "r"(a[0]), "r"(a[1]), "r"(a[2]), "r"(a[3]), "r"(b[0]), "r"(b[1]));
}
__device__ __forceinline__ void fma4(float4& a, float v, const float4& m) {
    a.x = fmaf(v, m.x, a.x);
    a.y = fmaf(v, m.y, a.y);
    a.z = fmaf(v, m.z, a.z);
    a.w = fmaf(v, m.w, a.w);
}

// ---------------- weight fp16 pack ----------------
__global__ void k_wpack(const float* __restrict__ W, int KP, int NC,
                        uint32_t* __restrict__ hi) {
    int idx = blockIdx.x * blockDim.x + threadIdx.x;
    if (idx >= KP * NC) return;
    int kp = idx / NC, n = idx - kp * NC;
    float x = W[(size_t)(2 * kp) * NC + n];
    float y = W[(size_t)(2 * kp + 1) * NC + n];
    hi[idx] = cvth2(x, y);
}

// emb -> fp16 into second half of combined image: wh16[row*384 + 192 + j]
__global__ void k_embh(const float* __restrict__ emb, uint32_t* __restrict__ wh16, int n) {
    int idx = blockIdx.x * blockDim.x + threadIdx.x;
    if (idx >= n * 192) return;
    int row = idx / 192, j = idx - row * 192;
    float2 v = *(const float2*)(emb + (size_t)row * HDIM + 2 * j);
    wh16[(size_t)row * 384 + 192 + j] = cvth2(v.x, v.y);
}

// ---------------- CSR build ----------------
__global__ void k_zero_i32(int* p, int n) {
    int i = blockIdx.x * blockDim.x + threadIdx.x;
    if (i < n) p[i] = 0;
}

__global__ void k_hist(const int* __restrict__ rows, int ne, int* __restrict__ cnt) {
    int e = blockIdx.x * blockDim.x + threadIdx.x;
    if (e < ne) atomicAdd(&cnt[rows[e]], 1);
}

__global__ void k_scan_excl(int* __restrict__ data, int n, int* __restrict__ wp) {
    __shared__ int sums[1024];
    int t = threadIdx.x;
    int C = (n + 1023) / 1024;
    int start = t * C;
    int end   = min(start + C, n);

    int s = 0;
    for (int i = start; i < end; i++) s += data[i];
    sums[t] = s;
    __syncthreads();

    for (int off = 1; off < 1024; off <<= 1) {
        int add = (t >= off) ? sums[t - off] : 0;
        __syncthreads();
        sums[t] += add;
        __syncthreads();
    }

    int run = sums[t] - s;
    for (int i = start; i < end; i++) {
        int c = data[i];
        data[i] = run;
        wp[i]   = run;
        run += c;
    }
    if (t == 1023) data[n] = sums[1023];
}

__global__ void k_scatter(const int* __restrict__ rows, const int* __restrict__ cols,
                          const float* __restrict__ vals, int ne,
                          int* __restrict__ wp, int* __restrict__ ci,
                          float* __restrict__ cv) {
    int e = blockIdx.x * blockDim.x + threadIdx.x;
    if (e < ne) {
        int pos = atomicAdd(&wp[rows[e]], 1);
        ci[pos] = cols[e];
        cv[pos] = vals[e];
    }
}

// ---------------- SpMM (CSR gather, float4, unroll-4, fp32 source) ----------------
__global__ void __launch_bounds__(96)
k_spmm(const int* __restrict__ rp, const int* __restrict__ ci,
       const float* __restrict__ cv, const float* __restrict__ M,
       float* __restrict__ out) {
    const int r = blockIdx.x;
    const int t = threadIdx.x;
    const int s = rp[r], e = rp[r + 1];
    const float4* __restrict__ M4 = (const float4*)M;
    float4 acc = make_float4(0.f, 0.f, 0.f, 0.f);

    int j = s;
    for (; j + 4 <= e; j += 4) {
        int   c0 = ci[j],     c1 = ci[j + 1], c2 = ci[j + 2], c3 = ci[j + 3];
        float v0 = cv[j],     v1 = cv[j + 1], v2 = cv[j + 2], v3 = cv[j + 3];
        float4 m0 = M4[(size_t)c0 * 96 + t];
        float4 m1 = M4[(size_t)c1 * 96 + t];
        float4 m2 = M4[(size_t)c2 * 96 + t];
        float4 m3 = M4[(size_t)c3 * 96 + t];
        fma4(acc, v0, m0);
        fma4(acc, v1, m1);
        fma4(acc, v2, m2);
        fma4(acc, v3, m3);
    }
    for (; j < e; j++) {
        float4 m = M4[(size_t)ci[j] * 96 + t];
        fma4(acc, cv[j], m);
    }
    ((float4*)(out + (size_t)r * HDIM))[t] = acc;
}

// SpMM over fp16 image [rows][192 u32]; thread t owns cols [4t, 4t+4) via one uint2/nnz.
__global__ void __launch_bounds__(96)
k_spmmh(const int* __restrict__ rp, const int* __restrict__ ci,
        const float* __restrict__ cv, const uint32_t* __restrict__ MH,
        float* __restrict__ out) {
    const int r = blockIdx.x;
    const int t = threadIdx.x;
    const int s = rp[r], e = rp[r + 1];
    const uint2* __restrict__ M2 = (const uint2*)MH;   // 96 uint2 per row

    float4 acc = make_float4(0.f, 0.f, 0.f, 0.f);
    auto accum = [&](float v, uint2 m) {
        float2 f0 = h2f2(m.x), f1 = h2f2(m.y);
        acc.x = fmaf(v, f0.x, acc.x);
        acc.y = fmaf(v, f0.y, acc.y);
        acc.z = fmaf(v, f1.x, acc.z);
        acc.w = fmaf(v, f1.y, acc.w);
    };

    int j = s;
    for (; j + 4 <= e; j += 4) {
        int   c0 = ci[j],  c1 = ci[j + 1], c2 = ci[j + 2], c3 = ci[j + 3];
        float v0 = cv[j],  v1 = cv[j + 1], v2 = cv[j + 2], v3 = cv[j + 3];
        uint2 m0 = M2[(size_t)c0 * 96 + t];
        uint2 m1 = M2[(size_t)c1 * 96 + t];
        uint2 m2 = M2[(size_t)c2 * 96 + t];
        uint2 m3 = M2[(size_t)c3 * 96 + t];
        accum(v0, m0);
        accum(v1, m1);
        accum(v2, m2);
        accum(v3, m3);
    }
    for (; j < e; j++) {
        uint2 m = M2[(size_t)ci[j] * 96 + t];
        accum(cv[j], m);
    }
    ((float4*)(out + (size_t)r * HDIM))[t] = acc;
}

// fused doc double-SpMM over combined fp16 image (one uint4 = 8 halves per thread/nnz).
__global__ void __launch_bounds__(96)
k_spmm2h(const int* __restrict__ rp, const int* __restrict__ ci,
         const float* __restrict__ cv, const uint32_t* __restrict__ MH,
         float* __restrict__ outA, float* __restrict__ outB) {
    const int r = blockIdx.x;
    const int t = threadIdx.x;
    const int s = rp[r], e = rp[r + 1];
    const uint4* __restrict__ M4 = (const uint4*)MH;   // 96 uint4 per row

    float acc[8];
#pragma unroll
    for (int i = 0; i < 8; i++) acc[i] = 0.f;

    auto accum = [&](float v, uint4 m) {
        float2 f0 = h2f2(m.x), f1 = h2f2(m.y), f2 = h2f2(m.z), f3 = h2f2(m.w);
        acc[0] = fmaf(v, f0.x, acc[0]);
        acc[1] = fmaf(v, f0.y, acc[1]);
        acc[2] = fmaf(v, f1.x, acc[2]);
        acc[3] = fmaf(v, f1.y, acc[3]);
        acc[4] = fmaf(v, f2.x, acc[4]);
        acc[5] = fmaf(v, f2.y, acc[5]);
        acc[6] = fmaf(v, f3.x, acc[6]);
        acc[7] = fmaf(v, f3.y, acc[7]);
    };

    int j = s;
    for (; j + 4 <= e; j += 4) {
        int   c0 = ci[j],  c1 = ci[j + 1], c2 = ci[j + 2], c3 = ci[j + 3];
        float v0 = cv[j],  v1 = cv[j + 1], v2 = cv[j + 2], v3 = cv[j + 3];
        uint4 m0 = M4[(size_t)c0 * 96 + t];
        uint4 m1 = M4[(size_t)c1 * 96 + t];
        uint4 m2 = M4[(size_t)c2 * 96 + t];
        uint4 m3 = M4[(size_t)c3 * 96 + t];
        accum(v0, m0);
        accum(v1, m1);
        accum(v2, m2);
        accum(v3, m3);
    }
    for (; j < e; j++) {
        uint4 m = M4[(size_t)ci[j] * 96 + t];
        accum(cv[j], m);
    }

    float* o = (t < 48) ? (outA + (size_t)r * HDIM + 8 * t)
                        : (outB + (size_t)r * HDIM + 8 * (t - 48));
    *(float4*)(o)     = make_float4(acc[0], acc[1], acc[2], acc[3]);
    *(float4*)(o + 4) = make_float4(acc[4], acc[5], acc[6], acc[7]);
}

// ---------------- fp16 split tensor-core GEMM with fused epilogues ----------------
// PASSES=2: A split a=ah+al (exact); PASSES=1: A rounded to fp16.
// out16 (LN_GELU only, non-null): store f16x2 into image with row stride s16 u32
// (skips the fp32 store entirely).
enum { EPI_LN_GELU = 0, EPI_GELU = 1, EPI_GATE = 2, EPI_GELU_LN = 3 };

template <int NCOLS, int EPI, int PASSES>
__global__ void __launch_bounds__(64 * (NCOLS / 48))
k_gemm(const float* __restrict__ A1, const float* __restrict__ A2,
       int K, int K1,
       const uint32_t* __restrict__ Wh,
       const float* __restrict__ bias,
       const float* __restrict__ gw, const float* __restrict__ bw,
       const float* __restrict__ aux1, const float* __restrict__ aux2,
       const float* __restrict__ res,
       float* __restrict__ out, uint32_t* __restrict__ out16, int s16, int M) {
    constexpr int NWN     = NCOLS / 48;
    constexpr int THREADS = 64 * NWN;
    constexpr int BM = 64, BK = 16;
    constexpr int MT = 2, NT = 6;
    constexpr int AV4 = BM * BK / 4;
    constexpr int BU4 = (8 * NCOLS) / 4;
    constexpr int BITER = (BU4 + THREADS - 1) / THREADS;
    constexpr int BROW = NCOLS + 8;

    __shared__ uint32_t AsH[BM][12];
    __shared__ uint32_t AsL[PASSES == 2 ? BM : 1][12];
    __shared__ uint32_t BsH[8][BROW];
    __shared__ float redS[2][32][NWN];
    __shared__ float redQ[2][32][NWN];

    const int tid  = threadIdx.x;
    const int lane = tid & 31;
    const int warp = tid >> 5;
    const int wm = warp & 1;
    const int wn = warp >> 1;
    const int g  = lane >> 2;
    const int t  = lane & 3;
    const int bm0 = blockIdx.x * BM;
    const int NC  = K / BK;

    float acc[MT][NT][4];
#pragma unroll
    for (int mt = 0; mt < MT; mt++)
#pragma unroll
        for (int nt = 0; nt < NT; nt++)
#pragma unroll
            for (int c = 0; c < 4; c++) acc[mt][nt][c] = 0.f;

    float4 pa;
    uint4  pbh[BITER];

    auto gload = [&](int k0) {
        const float* Ab;
        int kc, AW;
        if (k0 < K1) { Ab = A1; kc = k0; AW = K1; }
        else         { Ab = A2; kc = k0 - K1; AW = K - K1; }
        if (tid < AV4) {
            int row = tid >> 2, f4 = tid & 3;
            int grow = bm0 + row;
            if (grow < M)
                pa = *(const float4*)(Ab + (size_t)grow * AW + kc + 4 * f4);
            else
                pa = make_float4(0.f, 0.f, 0.f, 0.f);
        }
        const uint4* bh = (const uint4*)(Wh + (size_t)(k0 / 2) * NCOLS);
#pragma unroll
        for (int i = 0; i < BITER; i++) {
            int idx = tid + i * THREADS;
            if (idx < BU4) pbh[i] = bh[idx];
        }
    };
    auto sstore = [&]() {
        if (tid < AV4) {
            int row = tid >> 2, f4 = tid & 3;
            if constexpr (PASSES == 2) {
                uint32_t h0, l0, h1, l1;
                hsplit2(pa.x, pa.y, h0, l0);
                hsplit2(pa.z, pa.w, h1, l1);
                AsH[row][2 * f4]     = h0;
                AsH[row][2 * f4 + 1] = h1;
                AsL[row][2 * f4]     = l0;
                AsL[row][2 * f4 + 1] = l1;
            } else {
                AsH[row][2 * f4]     = cvth2(pa.x, pa.y);
                AsH[row][2 * f4 + 1] = cvth2(pa.z, pa.w);
            }
        }
#pragma unroll
        for (int i = 0; i < BITER; i++) {
            int idx = tid + i * THREADS;
            if (idx < BU4) {
                int off = 4 * idx;
                int r = off / NCOLS, n = off - r * NCOLS;
                *(uint4*)&BsH[r][n] = pbh[i];
            }
        }
    };

    gload(0);
    sstore();
    __syncthreads();

    for (int c = 0; c < NC; c++) {
        if (c + 1 < NC) gload((c + 1) * BK);

        uint32_t ah[MT][4], bh[NT][2];
#pragma unroll
        for (int mt = 0; mt < MT; mt++) {
            int r0 = wm * 32 + mt * 16;
            ah[mt][0] = AsH[r0 + g][t];
            ah[mt][1] = AsH[r0 + g + 8][t];
            ah[mt][2] = AsH[r0 + g][t + 4];
            ah[mt][3] = AsH[r0 + g + 8][t + 4];
        }
#pragma unroll
        for (int nt = 0; nt < NT; nt++) {
            int n0 = wn * 48 + nt * 8 + g;
            bh[nt][0] = BsH[t][n0];
            bh[nt][1] = BsH[t + 4][n0];
        }

#pragma unroll
        for (int nt = 0; nt < NT; nt++)
#pragma unroll
            for (int mt = 0; mt < MT; mt++)
                mma_f16(acc[mt][nt], ah[mt], bh[nt]);

        if constexpr (PASSES == 2) {
            uint32_t al[MT][4];
#pragma unroll
            for (int mt = 0; mt < MT; mt++) {
                int r0 = wm * 32 + mt * 16;
                al[mt][0] = AsL[r0 + g][t];
                al[mt][1] = AsL[r0 + g + 8][t];
                al[mt][2] = AsL[r0 + g][t + 4];
                al[mt][3] = AsL[r0 + g + 8][t + 4];
            }
#pragma unroll
            for (int nt = 0; nt < NT; nt++)
#pragma unroll
                for (int mt = 0; mt < MT; mt++)
                    mma_f16(acc[mt][nt], al[mt], bh[nt]);
        }

        __syncthreads();
        if (c + 1 < NC) {
            sstore();
            __syncthreads();
        }
    }

    // -------- epilogues --------
    // acc[mt][nt][c]: row = wm*32 + mt*16 + 8*(c>>1) + g ; col = wn*48 + nt*8 + 2*t + (c&1)
    if constexpr (EPI == EPI_GELU) {
#pragma unroll
        for (int mt = 0; mt < MT; mt++)
#pragma unroll
            for (int d = 0; d < 2; d++) {
                int grow = bm0 + wm * 32 + mt * 16 + 8 * d + g;
                if (grow >= M) continue;
#pragma unroll
                for (int nt = 0; nt < NT; nt++) {
                    int col = wn * 48 + nt * 8 + 2 * t;
                    float v0 = acc[mt][nt][2 * d]     + (bias ? bias[col]     : 0.f);
                    float v1 = acc[mt][nt][2 * d + 1] + (bias ? bias[col + 1] : 0.f);
                    *(float2*)&out[(size_t)grow * NCOLS + col] =
                        make_float2(gelu_exact(v0), gelu_exact(v1));
                }
            }
    } else if constexpr (EPI == EPI_GATE) {
#pragma unroll
        for (int mt = 0; mt < MT; mt++)
#pragma unroll
            for (int d = 0; d < 2; d++) {
                int grow = bm0 + wm * 32 + mt * 16 + 8 * d + g;
                if (grow >= M) continue;
#pragma unroll
                for (int nt = 0; nt < NT; nt++) {
                    int col = wn * 48 + nt * 8 + 2 * t;
                    size_t idx = (size_t)grow * NCOLS + col;
                    float s0 = sigmoidf_(acc[mt][nt][2 * d]     + bias[col]);
                    float s1 = sigmoidf_(acc[mt][nt][2 * d + 1] + bias[col + 1]);
                    float2 h1 = *(const float2*)&aux1[idx];
                    float2 h0 = *(const float2*)&aux2[idx];
                    *(float2*)&out[idx] = make_float2(
                        s0 * h1.x + (1.f - s0) * h0.x,
                        s1 * h1.y + (1.f - s1) * h0.y);
                }
            }
    } else {
        float sm_[MT][2], sq_[MT][2];
#pragma unroll
        for (int mt = 0; mt < MT; mt++)
#pragma unroll
            for (int d = 0; d < 2; d++) { sm_[mt][d] = 0.f; sq_[mt][d] = 0.f; }

#pragma unroll
        for (int mt = 0; mt < MT; mt++)
#pragma unroll
            for (int nt = 0; nt < NT; nt++) {
                int col = wn * 48 + nt * 8 + 2 * t;
#pragma unroll
                for (int d = 0; d < 2; d++) {
                    float v0 = acc[mt][nt][2 * d];
                    float v1 = acc[mt][nt][2 * d + 1];
                    if constexpr (EPI == EPI_GELU_LN) {
                        v0 = gelu_exact(v0 + bias[col]);
                        v1 = gelu_exact(v1 + bias[col + 1]);
                        acc[mt][nt][2 * d] = v0;
                        acc[mt][nt][2 * d + 1] = v1;
                    }
                    sm_[mt][d] += v0 + v1;
                    sq_[mt][d] += v0 * v0 + v1 * v1;
                }
            }
#pragma unroll
        for (int mt = 0; mt < MT; mt++)
#pragma unroll
            for (int d = 0; d < 2; d++) {
                float s = sm_[mt][d], q = sq_[mt][d];
                s += __shfl_xor_sync(0xffffffffu, s, 1);
                q += __shfl_xor_sync(0xffffffffu, q, 1);
                s += __shfl_xor_sync(0xffffffffu, s, 2);
                q += __shfl_xor_sync(0xffffffffu, q, 2);
                sm_[mt][d] = s; sq_[mt][d] = q;
            }
        if (t == 0) {
#pragma unroll
            for (int mt = 0; mt < MT; mt++)
#pragma unroll
                for (int d = 0; d < 2; d++) {
                    int rr = mt * 16 + 8 * d + g;
                    redS[wm][rr][wn] = sm_[mt][d];
                    redQ[wm][rr][wn] = sq_[mt][d];
                }
        }
        __syncthreads();
#pragma unroll
        for (int mt = 0; mt < MT; mt++)
#pragma unroll
            for (int d = 0; d < 2; d++) {
                int rr = mt * 16 + 8 * d + g;
                float S = 0.f, Q = 0.f;
#pragma unroll
                for (int w = 0; w < NWN; w++) { S += redS[wm][rr][w]; Q += redQ[wm][rr][w]; }
                float mean = S * (1.0f / NCOLS);
                float var  = Q * (1.0f / NCOLS) - mean * mean;
                float rstd = rsqrtf(var + LN_EPS);
                int grow = bm0 + wm * 32 + rr;
                if (grow >= M) continue;
#pragma unroll
                for (int nt = 0; nt < NT; nt++) {
                    int col = wn * 48 + nt * 8 + 2 * t;
                    float nv0 = (acc[mt][nt][2 * d]     - mean) * rstd * gw[col]     + bw[col];
                    float nv1 = (acc[mt][nt][2 * d + 1] - mean) * rstd * gw[col + 1] + bw[col + 1];
                    float o0, o1;
                    if constexpr (EPI == EPI_LN_GELU) {
                        o0 = gelu_exact(nv0);
                        o1 = gelu_exact(nv1);
                        if (res) {
                            float2 rv = *(const float2*)&res[(size_t)grow * NCOLS + col];
                            o0 = (1.f - ALPHA) * rv.x + ALPHA * o0;
                            o1 = (1.f - ALPHA) * rv.y + ALPHA * o1;
                        }
                    } else {
                        o0 = nv0; o1 = nv1;
                    }
                    if (EPI == EPI_LN_GELU && out16) {
                        out16[(size_t)grow * s16 + (col >> 1)] = cvth2(o0, o1);
                    } else {
                        *(float2*)&out[(size_t)grow * NCOLS + col] = make_float2(o0, o1);
                    }
                }
            }
    }
}

// ---------------- final tiny classifier ----------------
__global__ void k_logits(const float* __restrict__ t2, const float* __restrict__ clsW,
                         const float* __restrict__ clsb, float* __restrict__ out, int D) {
    int warp = (blockIdx.x * blockDim.x + threadIdx.x) >> 5;
    int lane = threadIdx.x & 31;
    if (warp >= D) return;
    const float* r = t2 + (size_t)warp * HHALF;
    float a0 = 0.f, a1 = 0.f;
    for (int k = lane; k < HHALF; k += 32) {
        float x = r[k];
        a0 = fmaf(x, clsW[2 * k],     a0);
        a1 = fmaf(x, clsW[2 * k + 1], a1);
    }
    for (int off = 16; off > 0; off >>= 1) {
        a0 += __shfl_down_sync(0xffffffffu, a0, off);
        a1 += __shfl_down_sync(0xffffffffu, a1, off);
    }
    if (lane == 0) {
        out[2 * warp]     = a0 + clsb[0];
        out[2 * warp + 1] = a1 + clsb[1];
    }
}

// ---------------- launch ----------------
extern "C" void kernel_launch(void* const* d_in, const int* in_sizes, int n_in,
                              void* d_out, int out_size) {
    const int*   A_rows  = (const int*)  d_in[0];
    const int*   A_cols  = (const int*)  d_in[1];
    const float* A_vals  = (const float*)d_in[2];
    const int*   X_rows  = (const int*)  d_in[3];
    const int*   X_cols  = (const int*)  d_in[4];
    const float* X_vals  = (const float*)d_in[5];
    const float* emb     = (const float*)d_in[7];
    const float* W1      = (const float*)d_in[8];
    const float* W2      = (const float*)d_in[9];
    const float* W3      = (const float*)d_in[10];
    const float* g1      = (const float*)d_in[11];
    const float* b1      = (const float*)d_in[12];
    const float* g2      = (const float*)d_in[13];
    const float* b2      = (const float*)d_in[14];
    const float* g3      = (const float*)d_in[15];
    const float* b3      = (const float*)d_in[16];
    const float* mlp_W1  = (const float*)d_in[17];
    const float* mlp_b1  = (const float*)d_in[18];
    const float* mlp_g   = (const float*)d_in[19];
    const float* mlp_bn  = (const float*)d_in[20];
    const float* mlp_W2  = (const float*)d_in[21];
    const float* mlp_b2  = (const float*)d_in[22];
    const float* cls_W   = (const float*)d_in[23];
    const float* cls_b   = (const float*)d_in[24];
    const float* gate_W1 = (const float*)d_in[25];
    const float* gate_b1 = (const float*)d_in[26];
    const float* gate_W2 = (const float*)d_in[27];
    const float* gate_b2 = (const float*)d_in[28];

    const int E   = in_sizes[0];
    const int NNZ = in_sizes[3];
    const int N   = in_sizes[7] / HDIM;
    const int D   = out_size / 2;
    float* out = (float*)d_out;

    float *buf1, *docH, *docH0, *hidden, *doc, *t2;
    int *Arp, *Awp, *Aci, *Xrp, *Xwp, *Xci;
    float *Av, *Xv;
    uint32_t *Wh, *h16, *wh16;
    cudaGetSymbolAddress((void**)&buf1,   g_buf1);
    cudaGetSymbolAddress((void**)&docH,   g_docH);
    cudaGetSymbolAddress((void**)&docH0,  g_docH0);
    cudaGetSymbolAddress((void**)&hidden, g_hidden);
    cudaGetSymbolAddress((void**)&doc,    g_doc);
    cudaGetSymbolAddress((void**)&t2,     g_t2);
    cudaGetSymbolAddress((void**)&Arp, g_Arp);
    cudaGetSymbolAddress((void**)&Awp, g_Awp);
    cudaGetSymbolAddress((void**)&Aci, g_Aci);
    cudaGetSymbolAddress((void**)&Av,  g_Av);
    cudaGetSymbolAddress((void**)&Xrp, g_Xrp);
    cudaGetSymbolAddress((void**)&Xwp, g_Xwp);
    cudaGetSymbolAddress((void**)&Xci, g_Xci);
    cudaGetSymbolAddress((void**)&Xv,  g_Xv);
    cudaGetSymbolAddress((void**)&Wh,  g_Wh);
    cudaGetSymbolAddress((void**)&h16,  g_h16);
    cudaGetSymbolAddress((void**)&wh16, g_wh16);

    const int gcnGrid = (N + 63) / 64;
    const int docGrid = (D + 63) / 64;

    // ---- pre-pack weights to fp16 + emb fp16 half of combined image ----
    {
        const int n384 = 192 * 384;
        k_wpack<<<(n384 + 255) / 256, 256>>>(W1,      192, 384, Wh + OFF_W1);
        k_wpack<<<(n384 + 255) / 256, 256>>>(W2,      192, 384, Wh + OFF_W2);
        k_wpack<<<(n384 + 255) / 256, 256>>>(W3,      192, 384, Wh + OFF_W3);
        k_wpack<<<(n384 + 255) / 256, 256>>>(gate_W2, 192, 384, Wh + OFF_GW2);
        k_wpack<<<(n384 + 255) / 256, 256>>>(mlp_W1,  192, 384, Wh + OFF_MW1);
        const int ngw1 = 384 * 384;
        k_wpack<<<(ngw1 + 255) / 256, 256>>>(gate_W1, 384, 384, Wh + OFF_GW1);
        k_wpack<<<(192 * 192 + 255) / 256, 256>>>(mlp_W2, 192, 192, Wh + OFF_MW2);
        k_embh <<<(N * 192 + 255) / 256, 256>>>(emb, wh16, N);
    }

    // ---- build CSR for A and X ----
    k_zero_i32<<<(N + 2 + 255) / 256, 256>>>(Arp, N + 1);
    k_hist    <<<(E + 255) / 256, 256>>>(A_rows, E, Arp);
    k_scan_excl<<<1, 1024>>>(Arp, N, Awp);
    k_scatter <<<(E + 255) / 256, 256>>>(A_rows, A_cols, A_vals, E, Awp, Aci, Av);

    k_zero_i32<<<(D + 2 + 255) / 256, 256>>>(Xrp, D + 1);
    k_hist    <<<(NNZ + 255) / 256, 256>>>(X_rows, NNZ, Xrp);
    k_scan_excl<<<1, 1024>>>(Xrp, D, Xwp);
    k_scatter <<<(NNZ + 255) / 256, 256>>>(X_rows, X_cols, X_vals, NNZ, Xwp, Xci, Xv);

    // ---- 3 residual GCN blocks (2-pass GEMMs) ----
    // block 1: fp32 emb gather; GEMM writes fp16-only intermediate h16
    k_spmm<<<N, 96>>>(Arp, Aci, Av, emb, buf1);
    k_gemm<HDIM, EPI_LN_GELU, 2><<<gcnGrid, 512>>>(buf1, nullptr, HDIM, HDIM,
        Wh + OFF_W1, nullptr, g1, b1, nullptr, nullptr, nullptr, nullptr, h16, 192, N);

    // block 2: fp16 gather of h16; GEMM writes h16 again
    k_spmmh<<<N, 96>>>(Arp, Aci, Av, h16, buf1);
    k_gemm<HDIM, EPI_LN_GELU, 2><<<gcnGrid, 512>>>(buf1, nullptr, HDIM, HDIM,
        Wh + OFF_W2, nullptr, g2, b2, nullptr, nullptr, nullptr, nullptr, h16, 192, N);

    // block 3: fp16 gather; GEMM writes word_H into combined image (stride 384)
    k_spmmh<<<N, 96>>>(Arp, Aci, Av, h16, buf1);
    k_gemm<HDIM, EPI_LN_GELU, 2><<<gcnGrid, 512>>>(buf1, nullptr, HDIM, HDIM,
        Wh + OFF_W3, nullptr, g3, b3, nullptr, nullptr, emb, nullptr, wh16, 384, N);

    // ---- doc aggregation over combined fp16 image ----
    k_spmm2h<<<D, 96>>>(Xrp, Xci, Xv, wh16, docH, docH0);

    // ---- doc head (1-pass GEMMs) ----
    k_gemm<HDIM, EPI_GELU, 1><<<docGrid, 512>>>(docH, docH0, 2 * HDIM, HDIM,
        Wh + OFF_GW1, gate_b1, nullptr, nullptr, nullptr, nullptr, nullptr, hidden, nullptr, 0, D);

    k_gemm<HDIM, EPI_GATE, 1><<<docGrid, 512>>>(hidden, nullptr, HDIM, HDIM,
        Wh + OFF_GW2, gate_b2, nullptr, nullptr, docH, docH0, nullptr, doc, nullptr, 0, D);

    k_gemm<HDIM, EPI_GELU_LN, 1><<<docGrid, 512>>>(doc, nullptr, HDIM, HDIM,
        Wh + OFF_MW1, mlp_b1, mlp_g, mlp_bn, nullptr, nullptr, nullptr, hidden, nullptr, 0, D);

    k_gemm<HHALF, EPI_GELU, 1><<<docGrid, 256>>>(hidden, nullptr, HDIM, HDIM,
        Wh + OFF_MW2, mlp_b2, nullptr, nullptr, nullptr, nullptr, nullptr, t2, nullptr, 0, D);

    // logits
    k_logits<<<(D + 7) / 8, 256>>>(t2, cls_W, cls_b, out, D);
}

// round 17
// speedup vs baseline: 1.3409x; 1.0012x over previous
#include <cuda_runtime.h>
#include <cuda_fp16.h>
#include <math.h>
#include <stdint.h>

// ---------------- problem constants ----------------
#define HDIM  384
#define HHALF 192
constexpr int   MAXN   = 40000;
constexpr int   MAXD   = 20000;
constexpr int   MAXE   = 800000;
constexpr int   MAXNNZ = 800000;
constexpr float ALPHA  = 0.65f;
constexpr float LN_EPS = 1e-5f;

// weight fp16 pool offsets (u32 units, layout [K/2][NCOLS] f16x2 k-pairs)
constexpr int OFF_W1  = 0;
constexpr int OFF_W2  = 73728;
constexpr int OFF_W3  = 147456;
constexpr int OFF_GW2 = 221184;
constexpr int OFF_MW1 = 294912;
constexpr int OFF_GW1 = 368640;   // K=768 x 384
constexpr int OFF_MW2 = 516096;   // 192 x 192
constexpr int WPOOL   = 552960;

// ---------------- static scratch ----------------
__device__ float g_buf1[(size_t)MAXN * HDIM];
__device__ float g_docH [(size_t)MAXD * HDIM];
__device__ float g_docH0[(size_t)MAXD * HDIM];
__device__ float g_hidden[(size_t)MAXD * HDIM];
__device__ float g_doc  [(size_t)MAXD * HDIM];
__device__ float g_t2   [(size_t)MAXD * HHALF];

__device__ __align__(16) uint32_t g_Wh[WPOOL];
// fp16 intermediate word image (blocks 1/2 output): [N][192] u32 = 384 halves/row
__device__ __align__(16) uint32_t g_h16[(size_t)MAXN * 192];
// combined fp16 doc-gather image: per word row, 768 halves = [word_H(384) | emb(384)]
__device__ __align__(16) uint32_t g_wh16[(size_t)MAXN * 384];

__device__ int   g_Arp[MAXN + 1];
__device__ int   g_Awp[MAXN + 1];
__device__ int   g_Aci[MAXE];
__device__ float g_Av [MAXE];
__device__ int   g_Xrp[MAXD + 1];
__device__ int   g_Xwp[MAXD + 1];
__device__ int   g_Xci[MAXNNZ];
__device__ float g_Xv [MAXNNZ];

// ---------------- helpers ----------------
__device__ __forceinline__ float gelu_exact(float x) {
    return 0.5f * x * (1.0f + erff(x * 0.70710678118654752f));
}
__device__ __forceinline__ float sigmoidf_(float x) {
    return 1.0f / (1.0f + __expf(-x));
}
__device__ __forceinline__ uint32_t cvth2(float x, float y) {
    __half2 h = __floats2half2_rn(x, y);
    return *reinterpret_cast<uint32_t*>(&h);
}
// split (x,y): hi = f16x2(x,y), lo = f16x2 of residuals
__device__ __forceinline__ void hsplit2(float x, float y, uint32_t& h, uint32_t& l) {
    __half2 hh = __floats2half2_rn(x, y);
    float2 f = __half22float2(hh);
    __half2 ll = __floats2half2_rn(x - f.x, y - f.y);
    h = *reinterpret_cast<uint32_t*>(&hh);
    l = *reinterpret_cast<uint32_t*>(&ll);
}
__device__ __forceinline__ float2 h2f2(uint32_t p) {
    __half2 h = *reinterpret_cast<__half2*>(&p);
    return __half22float2(h);
}
__device__ __forceinline__ void mma_f16(float* d, const uint32_t* a, const uint32_t* b) {
    asm volatile(
        "mma.sync.aligned.m16n8k16.row.col.f32.f16.f16.f32 "
        "{%0,%1,%2,%3}, {%4,%5,%6,%7}, {%8,%9}, {%0,%1,%2,%3};"
        : "+f"(d[0]), "+f"(d[1]), "+f"(d[2]), "+f"(d[3])
        : "r"(a[0]), "r"(a[1]), "r"(a[2]), "r"(a[3]), "r"(b[0]), "r"(b[1]));
}
__device__ __forceinline__ void fma4(float4& a, float v, const float4& m) {
    a.x = fmaf(v, m.x, a.x);
    a.y = fmaf(v, m.y, a.y);
    a.z = fmaf(v, m.z, a.z);
    a.w = fmaf(v, m.w, a.w);
}

// ---------------- weight fp16 pack ----------------
__global__ void k_wpack(const float* __restrict__ W, int KP, int NC,
                        uint32_t* __restrict__ hi) {
    int idx = blockIdx.x * blockDim.x + threadIdx.x;
    if (idx >= KP * NC) return;
    int kp = idx / NC, n = idx - kp * NC;
    float x = W[(size_t)(2 * kp) * NC + n];
    float y = W[(size_t)(2 * kp + 1) * NC + n];
    hi[idx] = cvth2(x, y);
}

// emb -> fp16 into second half of combined image: wh16[row*384 + 192 + j]
__global__ void k_embh(const float* __restrict__ emb, uint32_t* __restrict__ wh16, int n) {
    int idx = blockIdx.x * blockDim.x + threadIdx.x;
    if (idx >= n * 192) return;
    int row = idx / 192, j = idx - row * 192;
    float2 v = *(const float2*)(emb + (size_t)row * HDIM + 2 * j);
    wh16[(size_t)row * 384 + 192 + j] = cvth2(v.x, v.y);
}

// ---------------- CSR build ----------------
__global__ void k_zero_i32(int* p, int n) {
    int i = blockIdx.x * blockDim.x + threadIdx.x;
    if (i < n) p[i] = 0;
}

__global__ void k_hist(const int* __restrict__ rows, int ne, int* __restrict__ cnt) {
    int e = blockIdx.x * blockDim.x + threadIdx.x;
    if (e < ne) atomicAdd(&cnt[rows[e]], 1);
}

__global__ void k_scan_excl(int* __restrict__ data, int n, int* __restrict__ wp) {
    __shared__ int sums[1024];
    int t = threadIdx.x;
    int C = (n + 1023) / 1024;
    int start = t * C;
    int end   = min(start + C, n);

    int s = 0;
    for (int i = start; i < end; i++) s += data[i];
    sums[t] = s;
    __syncthreads();

    for (int off = 1; off < 1024; off <<= 1) {
        int add = (t >= off) ? sums[t - off] : 0;
        __syncthreads();
        sums[t] += add;
        __syncthreads();
    }

    int run = sums[t] - s;
    for (int i = start; i < end; i++) {
        int c = data[i];
        data[i] = run;
        wp[i]   = run;
        run += c;
    }
    if (t == 1023) data[n] = sums[1023];
}

__global__ void k_scatter(const int* __restrict__ rows, const int* __restrict__ cols,
                          const float* __restrict__ vals, int ne,
                          int* __restrict__ wp, int* __restrict__ ci,
                          float* __restrict__ cv) {
    int e = blockIdx.x * blockDim.x + threadIdx.x;
    if (e < ne) {
        int pos = atomicAdd(&wp[rows[e]], 1);
        ci[pos] = cols[e];
        cv[pos] = vals[e];
    }
}

// ---------------- SpMM over fp16 image; thread t owns 4 cols via one uint2/nnz ----------------
// MH rows have stride `stride` uint2; this SpMM reads uint2s [off + t] of each row.
__global__ void __launch_bounds__(96)
k_spmmh(const int* __restrict__ rp, const int* __restrict__ ci,
        const float* __restrict__ cv, const uint32_t* __restrict__ MH,
        int stride, int off, float* __restrict__ out) {
    const int r = blockIdx.x;
    const int t = threadIdx.x;
    const int s = rp[r], e = rp[r + 1];
    const uint2* __restrict__ M2 = (const uint2*)MH;

    float4 acc = make_float4(0.f, 0.f, 0.f, 0.f);
    auto accum = [&](float v, uint2 m) {
        float2 f0 = h2f2(m.x), f1 = h2f2(m.y);
        acc.x = fmaf(v, f0.x, acc.x);
        acc.y = fmaf(v, f0.y, acc.y);
        acc.z = fmaf(v, f1.x, acc.z);
        acc.w = fmaf(v, f1.y, acc.w);
    };

    int j = s;
    for (; j + 4 <= e; j += 4) {
        int   c0 = ci[j],  c1 = ci[j + 1], c2 = ci[j + 2], c3 = ci[j + 3];
        float v0 = cv[j],  v1 = cv[j + 1], v2 = cv[j + 2], v3 = cv[j + 3];
        uint2 m0 = M2[(size_t)c0 * stride + off + t];
        uint2 m1 = M2[(size_t)c1 * stride + off + t];
        uint2 m2 = M2[(size_t)c2 * stride + off + t];
        uint2 m3 = M2[(size_t)c3 * stride + off + t];
        accum(v0, m0);
        accum(v1, m1);
        accum(v2, m2);
        accum(v3, m3);
    }
    for (; j < e; j++) {
        uint2 m = M2[(size_t)ci[j] * stride + off + t];
        accum(cv[j], m);
    }
    ((float4*)(out + (size_t)r * HDIM))[t] = acc;
}

// fused doc double-SpMM over combined fp16 image (one uint4 = 8 halves per thread/nnz).
__global__ void __launch_bounds__(96)
k_spmm2h(const int* __restrict__ rp, const int* __restrict__ ci,
         const float* __restrict__ cv, const uint32_t* __restrict__ MH,
         float* __restrict__ outA, float* __restrict__ outB) {
    const int r = blockIdx.x;
    const int t = threadIdx.x;
    const int s = rp[r], e = rp[r + 1];
    const uint4* __restrict__ M4 = (const uint4*)MH;   // 96 uint4 per row

    float acc[8];
#pragma unroll
    for (int i = 0; i < 8; i++) acc[i] = 0.f;

    auto accum = [&](float v, uint4 m) {
        float2 f0 = h2f2(m.x), f1 = h2f2(m.y), f2 = h2f2(m.z), f3 = h2f2(m.w);
        acc[0] = fmaf(v, f0.x, acc[0]);
        acc[1] = fmaf(v, f0.y, acc[1]);
        acc[2] = fmaf(v, f1.x, acc[2]);
        acc[3] = fmaf(v, f1.y, acc[3]);
        acc[4] = fmaf(v, f2.x, acc[4]);
        acc[5] = fmaf(v, f2.y, acc[5]);
        acc[6] = fmaf(v, f3.x, acc[6]);
        acc[7] = fmaf(v, f3.y, acc[7]);
    };

    int j = s;
    for (; j + 4 <= e; j += 4) {
        int   c0 = ci[j],  c1 = ci[j + 1], c2 = ci[j + 2], c3 = ci[j + 3];
        float v0 = cv[j],  v1 = cv[j + 1], v2 = cv[j + 2], v3 = cv[j + 3];
        uint4 m0 = M4[(size_t)c0 * 96 + t];
        uint4 m1 = M4[(size_t)c1 * 96 + t];
        uint4 m2 = M4[(size_t)c2 * 96 + t];
        uint4 m3 = M4[(size_t)c3 * 96 + t];
        accum(v0, m0);
        accum(v1, m1);
        accum(v2, m2);
        accum(v3, m3);
    }
    for (; j < e; j++) {
        uint4 m = M4[(size_t)ci[j] * 96 + t];
        accum(cv[j], m);
    }

    float* o = (t < 48) ? (outA + (size_t)r * HDIM + 8 * t)
                        : (outB + (size_t)r * HDIM + 8 * (t - 48));
    *(float4*)(o)     = make_float4(acc[0], acc[1], acc[2], acc[3]);
    *(float4*)(o + 4) = make_float4(acc[4], acc[5], acc[6], acc[7]);
}

// ---------------- fp16 split tensor-core GEMM with fused epilogues ----------------
// PASSES=2: A split a=ah+al (exact); PASSES=1: A rounded to fp16.
// out16 (LN_GELU only, non-null): store f16x2 into image with row stride s16 u32.
enum { EPI_LN_GELU = 0, EPI_GELU = 1, EPI_GATE = 2, EPI_GELU_LN = 3 };

template <int NCOLS, int EPI, int PASSES>
__global__ void __launch_bounds__(64 * (NCOLS / 48))
k_gemm(const float* __restrict__ A1, const float* __restrict__ A2,
       int K, int K1,
       const uint32_t* __restrict__ Wh,
       const float* __restrict__ bias,
       const float* __restrict__ gw, const float* __restrict__ bw,
       const float* __restrict__ aux1, const float* __restrict__ aux2,
       const float* __restrict__ res,
       float* __restrict__ out, uint32_t* __restrict__ out16, int s16, int M) {
    constexpr int NWN     = NCOLS / 48;
    constexpr int THREADS = 64 * NWN;
    constexpr int BM = 64, BK = 16;
    constexpr int MT = 2, NT = 6;
    constexpr int AV4 = BM * BK / 4;
    constexpr int BU4 = (8 * NCOLS) / 4;
    constexpr int BITER = (BU4 + THREADS - 1) / THREADS;
    constexpr int BROW = NCOLS + 8;

    __shared__ uint32_t AsH[BM][12];
    __shared__ uint32_t AsL[PASSES == 2 ? BM : 1][12];
    __shared__ uint32_t BsH[8][BROW];
    __shared__ float redS[2][32][NWN];
    __shared__ float redQ[2][32][NWN];

    const int tid  = threadIdx.x;
    const int lane = tid & 31;
    const int warp = tid >> 5;
    const int wm = warp & 1;
    const int wn = warp >> 1;
    const int g  = lane >> 2;
    const int t  = lane & 3;
    const int bm0 = blockIdx.x * BM;
    const int NC  = K / BK;

    float acc[MT][NT][4];
#pragma unroll
    for (int mt = 0; mt < MT; mt++)
#pragma unroll
        for (int nt = 0; nt < NT; nt++)
#pragma unroll
            for (int c = 0; c < 4; c++) acc[mt][nt][c] = 0.f;

    float4 pa;
    uint4  pbh[BITER];

    auto gload = [&](int k0) {
        const float* Ab;
        int kc, AW;
        if (k0 < K1) { Ab = A1; kc = k0; AW = K1; }
        else         { Ab = A2; kc = k0 - K1; AW = K - K1; }
        if (tid < AV4) {
            int row = tid >> 2, f4 = tid & 3;
            int grow = bm0 + row;
            if (grow < M)
                pa = *(const float4*)(Ab + (size_t)grow * AW + kc + 4 * f4);
            else
                pa = make_float4(0.f, 0.f, 0.f, 0.f);
        }
        const uint4* bh = (const uint4*)(Wh + (size_t)(k0 / 2) * NCOLS);
#pragma unroll
        for (int i = 0; i < BITER; i++) {
            int idx = tid + i * THREADS;
            if (idx < BU4) pbh[i] = bh[idx];
        }
    };
    auto sstore = [&]() {
        if (tid < AV4) {
            int row = tid >> 2, f4 = tid & 3;
            if constexpr (PASSES == 2) {
                uint32_t h0, l0, h1, l1;
                hsplit2(pa.x, pa.y, h0, l0);
                hsplit2(pa.z, pa.w, h1, l1);
                AsH[row][2 * f4]     = h0;
                AsH[row][2 * f4 + 1] = h1;
                AsL[row][2 * f4]     = l0;
                AsL[row][2 * f4 + 1] = l1;
            } else {
                AsH[row][2 * f4]     = cvth2(pa.x, pa.y);
                AsH[row][2 * f4 + 1] = cvth2(pa.z, pa.w);
            }
        }
#pragma unroll
        for (int i = 0; i < BITER; i++) {
            int idx = tid + i * THREADS;
            if (idx < BU4) {
                int off = 4 * idx;
                int r = off / NCOLS, n = off - r * NCOLS;
                *(uint4*)&BsH[r][n] = pbh[i];
            }
        }
    };

    gload(0);
    sstore();
    __syncthreads();

    for (int c = 0; c < NC; c++) {
        if (c + 1 < NC) gload((c + 1) * BK);

        uint32_t ah[MT][4], bh[NT][2];
#pragma unroll
        for (int mt = 0; mt < MT; mt++) {
            int r0 = wm * 32 + mt * 16;
            ah[mt][0] = AsH[r0 + g][t];
            ah[mt][1] = AsH[r0 + g + 8][t];
            ah[mt][2] = AsH[r0 + g][t + 4];
            ah[mt][3] = AsH[r0 + g + 8][t + 4];
        }
#pragma unroll
        for (int nt = 0; nt < NT; nt++) {
            int n0 = wn * 48 + nt * 8 + g;
            bh[nt][0] = BsH[t][n0];
            bh[nt][1] = BsH[t + 4][n0];
        }

#pragma unroll
        for (int nt = 0; nt < NT; nt++)
#pragma unroll
            for (int mt = 0; mt < MT; mt++)
                mma_f16(acc[mt][nt], ah[mt], bh[nt]);

        if constexpr (PASSES == 2) {
            uint32_t al[MT][4];
#pragma unroll
            for (int mt = 0; mt < MT; mt++) {
                int r0 = wm * 32 + mt * 16;
                al[mt][0] = AsL[r0 + g][t];
                al[mt][1] = AsL[r0 + g + 8][t];
                al[mt][2] = AsL[r0 + g][t + 4];
                al[mt][3] = AsL[r0 + g + 8][t + 4];
            }
#pragma unroll
            for (int nt = 0; nt < NT; nt++)
#pragma unroll
                for (int mt = 0; mt < MT; mt++)
                    mma_f16(acc[mt][nt], al[mt], bh[nt]);
        }

        __syncthreads();
        if (c + 1 < NC) {
            sstore();
            __syncthreads();
        }
    }

    // -------- epilogues --------
    // acc[mt][nt][c]: row = wm*32 + mt*16 + 8*(c>>1) + g ; col = wn*48 + nt*8 + 2*t + (c&1)
    if constexpr (EPI == EPI_GELU) {
#pragma unroll
        for (int mt = 0; mt < MT; mt++)
#pragma unroll
            for (int d = 0; d < 2; d++) {
                int grow = bm0 + wm * 32 + mt * 16 + 8 * d + g;
                if (grow >= M) continue;
#pragma unroll
                for (int nt = 0; nt < NT; nt++) {
                    int col = wn * 48 + nt * 8 + 2 * t;
                    float v0 = acc[mt][nt][2 * d]     + (bias ? bias[col]     : 0.f);
                    float v1 = acc[mt][nt][2 * d + 1] + (bias ? bias[col + 1] : 0.f);
                    *(float2*)&out[(size_t)grow * NCOLS + col] =
                        make_float2(gelu_exact(v0), gelu_exact(v1));
                }
            }
    } else if constexpr (EPI == EPI_GATE) {
#pragma unroll
        for (int mt = 0; mt < MT; mt++)
#pragma unroll
            for (int d = 0; d < 2; d++) {
                int grow = bm0 + wm * 32 + mt * 16 + 8 * d + g;
                if (grow >= M) continue;
#pragma unroll
                for (int nt = 0; nt < NT; nt++) {
                    int col = wn * 48 + nt * 8 + 2 * t;
                    size_t idx = (size_t)grow * NCOLS + col;
                    float s0 = sigmoidf_(acc[mt][nt][2 * d]     + bias[col]);
                    float s1 = sigmoidf_(acc[mt][nt][2 * d + 1] + bias[col + 1]);
                    float2 h1 = *(const float2*)&aux1[idx];
                    float2 h0 = *(const float2*)&aux2[idx];
                    *(float2*)&out[idx] = make_float2(
                        s0 * h1.x + (1.f - s0) * h0.x,
                        s1 * h1.y + (1.f - s1) * h0.y);
                }
            }
    } else {
        float sm_[MT][2], sq_[MT][2];
#pragma unroll
        for (int mt = 0; mt < MT; mt++)
#pragma unroll
            for (int d = 0; d < 2; d++) { sm_[mt][d] = 0.f; sq_[mt][d] = 0.f; }

#pragma unroll
        for (int mt = 0; mt < MT; mt++)
#pragma unroll
            for (int nt = 0; nt < NT; nt++) {
                int col = wn * 48 + nt * 8 + 2 * t;
#pragma unroll
                for (int d = 0; d < 2; d++) {
                    float v0 = acc[mt][nt][2 * d];
                    float v1 = acc[mt][nt][2 * d + 1];
                    if constexpr (EPI == EPI_GELU_LN) {
                        v0 = gelu_exact(v0 + bias[col]);
                        v1 = gelu_exact(v1 + bias[col + 1]);
                        acc[mt][nt][2 * d] = v0;
                        acc[mt][nt][2 * d + 1] = v1;
                    }
                    sm_[mt][d] += v0 + v1;
                    sq_[mt][d] += v0 * v0 + v1 * v1;
                }
            }
#pragma unroll
        for (int mt = 0; mt < MT; mt++)
#pragma unroll
            for (int d = 0; d < 2; d++) {
                float s = sm_[mt][d], q = sq_[mt][d];
                s += __shfl_xor_sync(0xffffffffu, s, 1);
                q += __shfl_xor_sync(0xffffffffu, q, 1);
                s += __shfl_xor_sync(0xffffffffu, s, 2);
                q += __shfl_xor_sync(0xffffffffu, q, 2);
                sm_[mt][d] = s; sq_[mt][d] = q;
            }
        if (t == 0) {
#pragma unroll
            for (int mt = 0; mt < MT; mt++)
#pragma unroll
                for (int d = 0; d < 2; d++) {
                    int rr = mt * 16 + 8 * d + g;
                    redS[wm][rr][wn] = sm_[mt][d];
                    redQ[wm][rr][wn] = sq_[mt][d];
                }
        }
        __syncthreads();
#pragma unroll
        for (int mt = 0; mt < MT; mt++)
#pragma unroll
            for (int d = 0; d < 2; d++) {
                int rr = mt * 16 + 8 * d + g;
                float S = 0.f, Q = 0.f;
#pragma unroll
                for (int w = 0; w < NWN; w++) { S += redS[wm][rr][w]; Q += redQ[wm][rr][w]; }
                float mean = S * (1.0f / NCOLS);
                float var  = Q * (1.0f / NCOLS) - mean * mean;
                float rstd = rsqrtf(var + LN_EPS);
                int grow = bm0 + wm * 32 + rr;
                if (grow >= M) continue;
#pragma unroll
                for (int nt = 0; nt < NT; nt++) {
                    int col = wn * 48 + nt * 8 + 2 * t;
                    float nv0 = (acc[mt][nt][2 * d]     - mean) * rstd * gw[col]     + bw[col];
                    float nv1 = (acc[mt][nt][2 * d + 1] - mean) * rstd * gw[col + 1] + bw[col + 1];
                    float o0, o1;
                    if constexpr (EPI == EPI_LN_GELU) {
                        o0 = gelu_exact(nv0);
                        o1 = gelu_exact(nv1);
                        if (res) {
                            float2 rv = *(const float2*)&res[(size_t)grow * NCOLS + col];
                            o0 = (1.f - ALPHA) * rv.x + ALPHA * o0;
                            o1 = (1.f - ALPHA) * rv.y + ALPHA * o1;
                        }
                    } else {
                        o0 = nv0; o1 = nv1;
                    }
                    if (EPI == EPI_LN_GELU && out16) {
                        out16[(size_t)grow * s16 + (col >> 1)] = cvth2(o0, o1);
                    } else {
                        *(float2*)&out[(size_t)grow * NCOLS + col] = make_float2(o0, o1);
                    }
                }
            }
    }
}

// ---------------- final tiny classifier ----------------
__global__ void k_logits(const float* __restrict__ t2, const float* __restrict__ clsW,
                         const float* __restrict__ clsb, float* __restrict__ out, int D) {
    int warp = (blockIdx.x * blockDim.x + threadIdx.x) >> 5;
    int lane = threadIdx.x & 31;
    if (warp >= D) return;
    const float* r = t2 + (size_t)warp * HHALF;
    float a0 = 0.f, a1 = 0.f;
    for (int k = lane; k < HHALF; k += 32) {
        float x = r[k];
        a0 = fmaf(x, clsW[2 * k],     a0);
        a1 = fmaf(x, clsW[2 * k + 1], a1);
    }
    for (int off = 16; off > 0; off >>= 1) {
        a0 += __shfl_down_sync(0xffffffffu, a0, off);
        a1 += __shfl_down_sync(0xffffffffu, a1, off);
    }
    if (lane == 0) {
        out[2 * warp]     = a0 + clsb[0];
        out[2 * warp + 1] = a1 + clsb[1];
    }
}

// ---------------- launch ----------------
extern "C" void kernel_launch(void* const* d_in, const int* in_sizes, int n_in,
                              void* d_out, int out_size) {
    const int*   A_rows  = (const int*)  d_in[0];
    const int*   A_cols  = (const int*)  d_in[1];
    const float* A_vals  = (const float*)d_in[2];
    const int*   X_rows  = (const int*)  d_in[3];
    const int*   X_cols  = (const int*)  d_in[4];
    const float* X_vals  = (const float*)d_in[5];
    const float* emb     = (const float*)d_in[7];
    const float* W1      = (const float*)d_in[8];
    const float* W2      = (const float*)d_in[9];
    const float* W3      = (const float*)d_in[10];
    const float* g1      = (const float*)d_in[11];
    const float* b1      = (const float*)d_in[12];
    const float* g2      = (const float*)d_in[13];
    const float* b2      = (const float*)d_in[14];
    const float* g3      = (const float*)d_in[15];
    const float* b3      = (const float*)d_in[16];
    const float* mlp_W1  = (const float*)d_in[17];
    const float* mlp_b1  = (const float*)d_in[18];
    const float* mlp_g   = (const float*)d_in[19];
    const float* mlp_bn  = (const float*)d_in[20];
    const float* mlp_W2  = (const float*)d_in[21];
    const float* mlp_b2  = (const float*)d_in[22];
    const float* cls_W   = (const float*)d_in[23];
    const float* cls_b   = (const float*)d_in[24];
    const float* gate_W1 = (const float*)d_in[25];
    const float* gate_b1 = (const float*)d_in[26];
    const float* gate_W2 = (const float*)d_in[27];
    const float* gate_b2 = (const float*)d_in[28];

    const int E   = in_sizes[0];
    const int NNZ = in_sizes[3];
    const int N   = in_sizes[7] / HDIM;
    const int D   = out_size / 2;
    float* out = (float*)d_out;

    float *buf1, *docH, *docH0, *hidden, *doc, *t2;
    int *Arp, *Awp, *Aci, *Xrp, *Xwp, *Xci;
    float *Av, *Xv;
    uint32_t *Wh, *h16, *wh16;
    cudaGetSymbolAddress((void**)&buf1,   g_buf1);
    cudaGetSymbolAddress((void**)&docH,   g_docH);
    cudaGetSymbolAddress((void**)&docH0,  g_docH0);
    cudaGetSymbolAddress((void**)&hidden, g_hidden);
    cudaGetSymbolAddress((void**)&doc,    g_doc);
    cudaGetSymbolAddress((void**)&t2,     g_t2);
    cudaGetSymbolAddress((void**)&Arp, g_Arp);
    cudaGetSymbolAddress((void**)&Awp, g_Awp);
    cudaGetSymbolAddress((void**)&Aci, g_Aci);
    cudaGetSymbolAddress((void**)&Av,  g_Av);
    cudaGetSymbolAddress((void**)&Xrp, g_Xrp);
    cudaGetSymbolAddress((void**)&Xwp, g_Xwp);
    cudaGetSymbolAddress((void**)&Xci, g_Xci);
    cudaGetSymbolAddress((void**)&Xv,  g_Xv);
    cudaGetSymbolAddress((void**)&Wh,  g_Wh);
    cudaGetSymbolAddress((void**)&h16,  g_h16);
    cudaGetSymbolAddress((void**)&wh16, g_wh16);

    const int gcnGrid = (N + 63) / 64;
    const int docGrid = (D + 63) / 64;

    // ---- pre-pack weights to fp16 + emb fp16 half of combined image ----
    {
        const int n384 = 192 * 384;
        k_wpack<<<(n384 + 255) / 256, 256>>>(W1,      192, 384, Wh + OFF_W1);
        k_wpack<<<(n384 + 255) / 256, 256>>>(W2,      192, 384, Wh + OFF_W2);
        k_wpack<<<(n384 + 255) / 256, 256>>>(W3,      192, 384, Wh + OFF_W3);
        k_wpack<<<(n384 + 255) / 256, 256>>>(gate_W2, 192, 384, Wh + OFF_GW2);
        k_wpack<<<(n384 + 255) / 256, 256>>>(mlp_W1,  192, 384, Wh + OFF_MW1);
        const int ngw1 = 384 * 384;
        k_wpack<<<(ngw1 + 255) / 256, 256>>>(gate_W1, 384, 384, Wh + OFF_GW1);
        k_wpack<<<(192 * 192 + 255) / 256, 256>>>(mlp_W2, 192, 192, Wh + OFF_MW2);
        k_embh <<<(N * 192 + 255) / 256, 256>>>(emb, wh16, N);
    }

    // ---- build CSR for A and X ----
    k_zero_i32<<<(N + 2 + 255) / 256, 256>>>(Arp, N + 1);
    k_hist    <<<(E + 255) / 256, 256>>>(A_rows, E, Arp);
    k_scan_excl<<<1, 1024>>>(Arp, N, Awp);
    k_scatter <<<(E + 255) / 256, 256>>>(A_rows, A_cols, A_vals, E, Awp, Aci, Av);

    k_zero_i32<<<(D + 2 + 255) / 256, 256>>>(Xrp, D + 1);
    k_hist    <<<(NNZ + 255) / 256, 256>>>(X_rows, NNZ, Xrp);
    k_scan_excl<<<1, 1024>>>(Xrp, D, Xwp);
    k_scatter <<<(NNZ + 255) / 256, 256>>>(X_rows, X_cols, X_vals, NNZ, Xwp, Xci, Xv);

    // ---- 3 residual GCN blocks (2-pass GEMMs, all-fp16 gathers) ----
    // block 1: fp16 emb gather from wh16 second half (stride 192 uint2, offset 96)
    k_spmmh<<<N, 96>>>(Arp, Aci, Av, wh16, 192, 96, buf1);
    k_gemm<HDIM, EPI_LN_GELU, 2><<<gcnGrid, 512>>>(buf1, nullptr, HDIM, HDIM,
        Wh + OFF_W1, nullptr, g1, b1, nullptr, nullptr, nullptr, nullptr, h16, 192, N);

    // block 2: fp16 gather of h16 (stride 96 uint2)
    k_spmmh<<<N, 96>>>(Arp, Aci, Av, h16, 96, 0, buf1);
    k_gemm<HDIM, EPI_LN_GELU, 2><<<gcnGrid, 512>>>(buf1, nullptr, HDIM, HDIM,
        Wh + OFF_W2, nullptr, g2, b2, nullptr, nullptr, nullptr, nullptr, h16, 192, N);

    // block 3: fp16 gather; GEMM writes word_H into combined image (stride 384)
    k_spmmh<<<N, 96>>>(Arp, Aci, Av, h16, 96, 0, buf1);
    k_gemm<HDIM, EPI_LN_GELU, 2><<<gcnGrid, 512>>>(buf1, nullptr, HDIM, HDIM,
        Wh + OFF_W3, nullptr, g3, b3, nullptr, nullptr, emb, nullptr, wh16, 384, N);

    // ---- doc aggregation over combined fp16 image ----
    k_spmm2h<<<D, 96>>>(Xrp, Xci, Xv, wh16, docH, docH0);

    // ---- doc head (1-pass GEMMs) ----
    k_gemm<HDIM, EPI_GELU, 1><<<docGrid, 512>>>(docH, docH0, 2 * HDIM, HDIM,
        Wh + OFF_GW1, gate_b1, nullptr, nullptr, nullptr, nullptr, nullptr, hidden, nullptr, 0, D);

    k_gemm<HDIM, EPI_GATE, 1><<<docGrid, 512>>>(hidden, nullptr, HDIM, HDIM,
        Wh + OFF_GW2, gate_b2, nullptr, nullptr, docH, docH0, nullptr, doc, nullptr, 0, D);

    k_gemm<HDIM, EPI_GELU_LN, 1><<<docGrid, 512>>>(doc, nullptr, HDIM, HDIM,
        Wh + OFF_MW1, mlp_b1, mlp_g, mlp_bn, nullptr, nullptr, nullptr, hidden, nullptr, 0, D);

    k_gemm<HHALF, EPI_GELU, 1><<<docGrid, 256>>>(hidden, nullptr, HDIM, HDIM,
        Wh + OFF_MW2, mlp_b2, nullptr, nullptr, nullptr, nullptr, nullptr, t2, nullptr, 0, D);

    // logits
    k_logits<<<(D + 7) / 8, 256>>>(t2, cls_W, cls_b, out, D);
}